// round 4
// baseline (speedup 1.0000x reference)
#include <cuda_runtime.h>
#include <math.h>

#define NPT 1024      // N tokens
#define CS_ 384
#define CZ_ 128
#define H_ 8
#define G_ 16
#define C_ 48
#define PV_ 12
#define CZ4_ 32
#define NSQ (NPT*NPT)

// ---------------- device scratch (no allocations allowed) ----------------
__device__ float g_qh  [NPT*H_*C_];     // rotated+scaled q  (n, h, 48)
__device__ float g_krot[NPT*H_*C_];     // rotated k         (n, h, 48)
__device__ float g_v   [NPT*H_*C_];     // v                 (n, h, 48)
__device__ float g_vpts[NPT*H_*PV_*3];  // v points          (n, h, p, coord)
__device__ float g_a   [H_*NSQ];        // attention logits/probs (h, n, m)
__device__ float g_zbar[NPT*H_*CZ_];    // sum_m a*z          (n, h, 128)
__device__ float g_feats[NPT*1024];     // concat features    (n, 1024)

// ---------------- K1: projections (q,k,v,v_pts) + rotation -----------------
// grid 128 blocks x 256 threads, 8 token rows per block.
__global__ void k_proj(const float* __restrict__ s, const float* __restrict__ rot,
                       const float* __restrict__ wq, const float* __restrict__ bq,
                       const float* __restrict__ wkv, const float* __restrict__ bkv,
                       const float* __restrict__ wkvp, const float* __restrict__ bkvp,
                       const float* __restrict__ gw)
{
    __shared__ float s_sm[8][CS_];
    __shared__ float qraw[8][CS_];
    __shared__ float kraw[8][CS_];
    __shared__ float rot_sm[8][9];
    __shared__ float hw_sm[G_];
    const int t  = threadIdx.x;
    const int n0 = blockIdx.x * 8;

    for (int e = t; e < 8*CS_; e += 256) ((float*)s_sm)[e] = s[n0*CS_ + e];
    for (int e = t; e < 72;     e += 256) ((float*)rot_sm)[e] = rot[n0*9 + e];
    if (t < G_) hw_sm[t] = 0.25f * log1pf(expf(gw[t])) * 0.57735026918962584f;
    __syncthreads();

    // 1440 useful output columns: 384 q | 768 kv | 288 v_pts. groups of 4.
    for (int gt = t; gt < 360; gt += 256) {
        const int c0 = gt * 4;
        float acc[4][8];
        #pragma unroll
        for (int j = 0; j < 4; j++)
            #pragma unroll
            for (int r = 0; r < 8; r++) acc[j][r] = 0.f;

        const float* w0; int stride; int cols[4];
        if (c0 < 384) {
            w0 = wq; stride = 384;
            #pragma unroll
            for (int j = 0; j < 4; j++) cols[j] = c0 + j;
        } else if (c0 < 1152) {
            w0 = wkv; stride = 768;
            #pragma unroll
            for (int j = 0; j < 4; j++) cols[j] = c0 - 384 + j;
        } else {
            w0 = wkvp; stride = 480;
            #pragma unroll
            for (int j = 0; j < 4; j++) {
                int tc = c0 - 1152 + j;
                int h = tc / 36, rr = tc % 36, p = rr / 3, cd = rr % 3;
                cols[j] = cd*160 + h*20 + 8 + p;   // v_pts columns of wkvp
            }
        }
        for (int k = 0; k < CS_; k++) {
            float wv[4];
            #pragma unroll
            for (int j = 0; j < 4; j++) wv[j] = w0[k*stride + cols[j]];
            #pragma unroll
            for (int r = 0; r < 8; r++) {
                float sv = s_sm[r][k];
                #pragma unroll
                for (int j = 0; j < 4; j++) acc[j][r] += sv * wv[j];
            }
        }
        #pragma unroll
        for (int j = 0; j < 4; j++) {
            int c = c0 + j;
            if (c < 384) {
                float b = bq[c];
                #pragma unroll
                for (int r = 0; r < 8; r++) qraw[r][c] = acc[j][r] + b;
            } else if (c < 1152) {
                int jj = c - 384; float b = bkv[jj];
                int h = jj / 96, rem = jj % 96;
                if (rem < 48) {
                    #pragma unroll
                    for (int r = 0; r < 8; r++) kraw[r][h*48 + rem] = acc[j][r] + b;
                } else {
                    #pragma unroll
                    for (int r = 0; r < 8; r++) g_v[(n0+r)*384 + h*48 + rem - 48] = acc[j][r] + b;
                }
            } else {
                int tc = c - 1152; float b = bkvp[cols[j]];
                #pragma unroll
                for (int r = 0; r < 8; r++) g_vpts[(n0+r)*288 + tc] = acc[j][r] + b;
            }
        }
    }
    __syncthreads();

    // rotation: qh = hw[g]/sqrt3 * R q ; krot = R k   (6144 scalar outputs)
    for (int task = t; task < 6144; task += 256) {
        int r = task / 768, rem = task % 768;
        int isK = rem >= 384;
        int e = isK ? rem - 384 : rem;
        int h = e / 48, g = (e % 48) / 3, i = e % 3;
        const float* src = isK ? &kraw[r][0] : &qraw[r][0];
        float v0 = src[h*48 + g*3 + 0];
        float v1 = src[h*48 + g*3 + 1];
        float v2 = src[h*48 + g*3 + 2];
        float val = rot_sm[r][i*3+0]*v0 + rot_sm[r][i*3+1]*v1 + rot_sm[r][i*3+2]*v2;
        if (isK) g_krot[(n0+r)*384 + e] = val;
        else     g_qh  [(n0+r)*384 + e] = val * hw_sm[g];
    }
}

// ---------------- K2a: qk logits  a[h,n,m] = qh[n,h,:].krot[m,h,:] ----------
__global__ void k_qk()
{
    const int h  = blockIdx.z;
    const int n0 = blockIdx.y * 64;
    const int m0 = blockIdx.x * 64;
    __shared__ float qs[64][49];
    __shared__ float ks[64][49];
    const int t = threadIdx.x;
    for (int e = t; e < 64*48; e += 256) {
        int r = e / 48, c = e % 48;
        qs[r][c] = g_qh  [(n0+r)*384 + h*48 + c];
        ks[r][c] = g_krot[(m0+r)*384 + h*48 + c];
    }
    __syncthreads();
    const int tx = t % 16, ty = t / 16;
    float acc[4][4] = {};
    for (int k = 0; k < 48; k++) {
        float aq[4], bk[4];
        #pragma unroll
        for (int i = 0; i < 4; i++) aq[i] = qs[ty*4+i][k];
        #pragma unroll
        for (int j = 0; j < 4; j++) bk[j] = ks[tx*4+j][k];
        #pragma unroll
        for (int i = 0; i < 4; i++)
            #pragma unroll
            for (int j = 0; j < 4; j++) acc[i][j] += aq[i] * bk[j];
    }
    #pragma unroll
    for (int i = 0; i < 4; i++)
        #pragma unroll
        for (int j = 0; j < 4; j++)
            g_a[h*NSQ + (n0+ty*4+i)*NPT + (m0+tx*4+j)] = acc[i][j];
}

// ---------------- K2b: stream z once, add sqrt(1/3)*(z.wb + bb) ------------
// grid (1024 n, 4 m-tiles) x 64 threads; each thread owns 4 m x 8 h.
__global__ void k_badd(const float* __restrict__ z, const float* __restrict__ wb,
                       const float* __restrict__ bb)
{
    __shared__ float z_sm[256*33];
    __shared__ float wb_sm[32*8];
    const int n  = blockIdx.x;
    const int m0 = blockIdx.y * 256;
    const int t  = threadIdx.x;
    float acc[4][8] = {};
    for (int cz0 = 0; cz0 < 128; cz0 += 32) {
        for (int e = t; e < 256*32; e += 64) {
            int row = e >> 5, c = e & 31;
            z_sm[row*33 + c] = z[(n*NPT + m0 + row)*128 + cz0 + c];
        }
        for (int e = t; e < 256; e += 64) wb_sm[e] = wb[(cz0 + (e>>3))*8 + (e&7)];
        __syncthreads();
        for (int c = 0; c < 32; c++) {
            float wbv[8];
            #pragma unroll
            for (int h = 0; h < 8; h++) wbv[h] = wb_sm[c*8 + h];
            #pragma unroll
            for (int i = 0; i < 4; i++) {
                float zv = z_sm[(t*4 + i)*33 + c];
                #pragma unroll
                for (int h = 0; h < 8; h++) acc[i][h] += zv * wbv[h];
            }
        }
        __syncthreads();
    }
    #pragma unroll
    for (int i = 0; i < 4; i++) {
        int m = m0 + t*4 + i;
        #pragma unroll
        for (int h = 0; h < 8; h++)
            g_a[h*NSQ + n*NPT + m] += 0.57735026918962584f * (acc[i][h] + bb[h]);
    }
}

// ---------------- K3: masked softmax over m -----------------
__global__ void k_softmax(const float* __restrict__ mask)
{
    const int bid = blockIdx.x;
    const int h = bid >> 10, n = bid & 1023;
    float* row = g_a + (size_t)h*NSQ + (size_t)n*NPT;
    const int t = threadIdx.x;
    const float mn = mask[n];
    float x[4]; float mx = -1e30f;
    #pragma unroll
    for (int j = 0; j < 4; j++) {
        int m = t + j*256;
        float xx = row[m] + 100000.0f * (mn * mask[m] - 1.0f);
        x[j] = xx; mx = fmaxf(mx, xx);
    }
    __shared__ float red[8];
    for (int o = 16; o; o >>= 1) mx = fmaxf(mx, __shfl_xor_sync(0xffffffffu, mx, o));
    if ((t & 31) == 0) red[t >> 5] = mx;
    __syncthreads();
    if (t == 0) { float r = red[0]; for (int w = 1; w < 8; w++) r = fmaxf(r, red[w]); red[0] = r; }
    __syncthreads();
    mx = red[0];
    __syncthreads();
    float sum = 0.f;
    #pragma unroll
    for (int j = 0; j < 4; j++) { x[j] = expf(x[j] - mx); sum += x[j]; }
    for (int o = 16; o; o >>= 1) sum += __shfl_xor_sync(0xffffffffu, sum, o);
    if ((t & 31) == 0) red[t >> 5] = sum;
    __syncthreads();
    if (t == 0) { float r = 0.f; for (int w = 0; w < 8; w++) r += red[w]; red[0] = r; }
    __syncthreads();
    const float inv = 1.0f / red[0];
    #pragma unroll
    for (int j = 0; j < 4; j++) row[t + j*256] = x[j] * inv;
}

// ---------------- K4a: zbar[n,h,cz] = sum_m a[h,n,m]*z[n,m,cz] -------------
// grid 1024 x 64 threads; thread owns 4 h x 4 cz.
__global__ void k_zbar(const float* __restrict__ z)
{
    __shared__ __align__(16) float z_sm[16*128];
    __shared__ float a_sm[8*16];
    const int n = blockIdx.x;
    const int t = threadIdx.x;
    const int hg  = t & 1;    // 2 groups of 4 heads
    const int czg = t >> 1;   // 32 groups of 4 cz
    float acc[4][4] = {};
    for (int m0 = 0; m0 < NPT; m0 += 16) {
        for (int e = t; e < 2048; e += 64)
            z_sm[e] = z[(n*NPT + m0 + (e >> 7))*128 + (e & 127)];
        for (int e = t; e < 128; e += 64)
            a_sm[e] = g_a[(e >> 4)*NSQ + n*NPT + m0 + (e & 15)];
        __syncthreads();
        for (int mm = 0; mm < 16; mm++) {
            float4 zv = *reinterpret_cast<const float4*>(&z_sm[mm*128 + czg*4]);
            float av[4];
            #pragma unroll
            for (int hi = 0; hi < 4; hi++) av[hi] = a_sm[(hg*4 + hi)*16 + mm];
            #pragma unroll
            for (int hi = 0; hi < 4; hi++) {
                acc[hi][0] += av[hi]*zv.x; acc[hi][1] += av[hi]*zv.y;
                acc[hi][2] += av[hi]*zv.z; acc[hi][3] += av[hi]*zv.w;
            }
        }
        __syncthreads();
    }
    #pragma unroll
    for (int hi = 0; hi < 4; hi++)
        #pragma unroll
        for (int ci = 0; ci < 4; ci++)
            g_zbar[n*1024 + (hg*4 + hi)*128 + czg*4 + ci] = acc[hi][ci];
}

// ---------------- K4b: o and o_pt = A @ [v | v_pts] per head ----------------
// grid (64 n-tiles, 8 h) x 96 threads; 16 rows x 96 cols (84 valid) per block.
__global__ void k_ov()
{
    __shared__ float a_sm[16*33];
    __shared__ __align__(16) float vv_sm[32*100];
    const int h  = blockIdx.y;
    const int n0 = blockIdx.x * 16;
    const int t  = threadIdx.x;           // 96
    const int rg = t / 24, cg = t % 24;   // 4x4 tile each
    float acc[4][4] = {};
    for (int m0 = 0; m0 < NPT; m0 += 32) {
        for (int e = t; e < 512; e += 96) {
            int r = e >> 5, mm = e & 31;
            a_sm[r*33 + mm] = g_a[h*NSQ + (n0 + r)*NPT + m0 + mm];
        }
        for (int e = t; e < 32*96; e += 96) {
            int mm = e / 96, c = e % 96;
            int m = m0 + mm;
            float val = 0.f;
            if (c < 48)       val = g_v[m*384 + h*48 + c];
            else if (c < 84)  val = g_vpts[m*288 + h*36 + (c - 48)];
            vv_sm[mm*100 + c] = val;
        }
        __syncthreads();
        for (int mm = 0; mm < 32; mm++) {
            float4 bv = *reinterpret_cast<const float4*>(&vv_sm[mm*100 + cg*4]);
            float av[4];
            #pragma unroll
            for (int i = 0; i < 4; i++) av[i] = a_sm[(rg*4 + i)*33 + mm];
            #pragma unroll
            for (int i = 0; i < 4; i++) {
                acc[i][0] += av[i]*bv.x; acc[i][1] += av[i]*bv.y;
                acc[i][2] += av[i]*bv.z; acc[i][3] += av[i]*bv.w;
            }
        }
        __syncthreads();
    }
    #pragma unroll
    for (int i = 0; i < 4; i++) {
        int n = n0 + rg*4 + i;
        #pragma unroll
        for (int j = 0; j < 4; j++) {
            int c = cg*4 + j;
            if (c < 48) {
                g_feats[n*1024 + h*48 + c] = acc[i][j];
            } else if (c < 84) {
                int p = (c - 48) / 3, coord = (c - 48) % 3;
                g_feats[n*1024 + 384 + coord*96 + h*12 + p] = acc[i][j];
            }
        }
    }
}

// ---------------- K5: o_pair = zbar@wdz + bdz, point norms ------------------
__global__ void k_pair_norm(const float* __restrict__ wdz, const float* __restrict__ bdz)
{
    __shared__ float zb[1024];
    const int n = blockIdx.x;
    const int t = threadIdx.x;  // 256
    for (int e = t; e < 1024; e += 256) zb[e] = g_zbar[n*1024 + e];
    __syncthreads();
    {
        const int h = t >> 5, d = t & 31;
        float acc = bdz[d];
        for (int cz = 0; cz < 128; cz++) acc += zb[h*128 + cz] * wdz[cz*32 + d];
        g_feats[n*1024 + 768 + t] = acc;
    }
    if (t < 96) {
        float x  = g_feats[n*1024 + 384 + t];
        float y  = g_feats[n*1024 + 480 + t];
        float zz = g_feats[n*1024 + 576 + t];
        g_feats[n*1024 + 672 + t] = sqrtf(x*x + y*y + zz*zz + 1e-8f);
    }
}

// ---------------- K6: out = feats @ wout + bout -----------------------------
// grid (4 j-tiles, 32 n-tiles) x 256 threads; block 32 n x 96 j; thread 4x3.
__global__ void k_out(const float* __restrict__ wout, const float* __restrict__ bout,
                      float* __restrict__ out)
{
    __shared__ float f_sm[32*65];
    __shared__ float w_sm[64*97];
    const int n0 = blockIdx.y * 32;
    const int j0 = blockIdx.x * 96;
    const int t  = threadIdx.x;
    const int rg = t >> 5, cg = t & 31;
    float acc[4][3] = {};
    for (int e0 = 0; e0 < 1024; e0 += 64) {
        for (int e = t; e < 2048; e += 256) {
            int r = e >> 6, k = e & 63;
            f_sm[r*65 + k] = g_feats[(n0 + r)*1024 + e0 + k];
        }
        for (int e = t; e < 6144; e += 256) {
            int k = e / 96, c = e % 96;
            w_sm[k*97 + c] = wout[(e0 + k)*384 + j0 + c];
        }
        __syncthreads();
        for (int k = 0; k < 64; k++) {
            float av[4], bv[3];
            #pragma unroll
            for (int i = 0; i < 4; i++) av[i] = f_sm[(rg*4 + i)*65 + k];
            #pragma unroll
            for (int j = 0; j < 3; j++) bv[j] = w_sm[k*97 + cg*3 + j];
            #pragma unroll
            for (int i = 0; i < 4; i++)
                #pragma unroll
                for (int j = 0; j < 3; j++) acc[i][j] += av[i] * bv[j];
        }
        __syncthreads();
    }
    #pragma unroll
    for (int i = 0; i < 4; i++) {
        int n = n0 + rg*4 + i;
        #pragma unroll
        for (int j = 0; j < 3; j++) {
            int c = j0 + cg*3 + j;
            out[n*384 + c] = acc[i][j] + bout[c];
        }
    }
}

// ---------------- launch ----------------------------------------------------
extern "C" void kernel_launch(void* const* d_in, const int* in_sizes, int n_in,
                              void* d_out, int out_size)
{
    const float* s    = (const float*)d_in[0];
    const float* z    = (const float*)d_in[1];
    const float* rot  = (const float*)d_in[2];
    const float* mask = (const float*)d_in[3];
    const float* wq   = (const float*)d_in[4];
    const float* bq   = (const float*)d_in[5];
    const float* wkv  = (const float*)d_in[6];
    const float* bkv  = (const float*)d_in[7];
    const float* wkvp = (const float*)d_in[8];
    const float* bkvp = (const float*)d_in[9];
    const float* wb   = (const float*)d_in[10];
    const float* bb   = (const float*)d_in[11];
    const float* wdz  = (const float*)d_in[12];
    const float* bdz  = (const float*)d_in[13];
    const float* wout = (const float*)d_in[14];
    const float* bout = (const float*)d_in[15];
    const float* gw   = (const float*)d_in[16];
    float* out = (float*)d_out;

    k_proj<<<128, 256>>>(s, rot, wq, bq, wkv, bkv, wkvp, bkvp, gw);
    k_qk<<<dim3(16, 16, 8), 256>>>();
    k_badd<<<dim3(1024, 4), 64>>>(z, wb, bb);
    k_softmax<<<8192, 256>>>(mask);
    k_zbar<<<1024, 64>>>(z);
    k_ov<<<dim3(64, 8), 96>>>();
    k_pair_norm<<<1024, 256>>>(wdz, bdz);
    k_out<<<dim3(4, 32), 256>>>(wout, bout, out);
}

// round 5
// speedup vs baseline: 1.0035x; 1.0035x over previous
#include <cuda_runtime.h>
#include <math.h>

#define NPT 1024      // N tokens
#define CS_ 384
#define CZ_ 128
#define H_ 8
#define G_ 16
#define C_ 48
#define PV_ 12
#define CZ4_ 32
#define NSQ (NPT*NPT)

// ---------------- device scratch (no allocations allowed) ----------------
__device__ float g_qh  [NPT*H_*C_];     // rotated+scaled q  (n, h, 48)
__device__ float g_krot[NPT*H_*C_];     // rotated k         (n, h, 48)
__device__ float g_v   [NPT*H_*C_];     // v                 (n, h, 48)
__device__ float g_vpts[NPT*H_*PV_*3];  // v points          (n, h, p, coord)
__device__ float g_a   [H_*NSQ];        // attention logits/probs (h, n, m)
__device__ float g_zbar[NPT*H_*CZ_];    // sum_m a*z          (n, h, 128)
__device__ float g_feats[NPT*1024];     // concat features    (n, 1024)

// ---------------- K1: projections (q,k,v,v_pts) + rotation -----------------
// grid 128 blocks x 256 threads, 8 token rows per block.
__global__ void k_proj(const float* __restrict__ s, const float* __restrict__ rot,
                       const float* __restrict__ wq, const float* __restrict__ bq,
                       const float* __restrict__ wkv, const float* __restrict__ bkv,
                       const float* __restrict__ wkvp, const float* __restrict__ bkvp,
                       const float* __restrict__ gw)
{
    __shared__ float s_sm[8][CS_];
    __shared__ float qraw[8][CS_];
    __shared__ float kraw[8][CS_];
    __shared__ float rot_sm[8][9];
    __shared__ float hw_sm[G_];
    const int t  = threadIdx.x;
    const int n0 = blockIdx.x * 8;

    for (int e = t; e < 8*CS_; e += 256) ((float*)s_sm)[e] = s[n0*CS_ + e];
    for (int e = t; e < 72;     e += 256) ((float*)rot_sm)[e] = rot[n0*9 + e];
    if (t < G_) hw_sm[t] = 0.25f * log1pf(expf(gw[t])) * 0.57735026918962584f;
    __syncthreads();

    // 1440 useful output columns: 384 q | 768 kv | 288 v_pts. groups of 4.
    for (int gt = t; gt < 360; gt += 256) {
        const int c0 = gt * 4;
        float acc[4][8];
        #pragma unroll
        for (int j = 0; j < 4; j++)
            #pragma unroll
            for (int r = 0; r < 8; r++) acc[j][r] = 0.f;

        const float* w0; int stride; int cols[4];
        if (c0 < 384) {
            w0 = wq; stride = 384;
            #pragma unroll
            for (int j = 0; j < 4; j++) cols[j] = c0 + j;
        } else if (c0 < 1152) {
            w0 = wkv; stride = 768;
            #pragma unroll
            for (int j = 0; j < 4; j++) cols[j] = c0 - 384 + j;
        } else {
            w0 = wkvp; stride = 480;
            #pragma unroll
            for (int j = 0; j < 4; j++) {
                int tc = c0 - 1152 + j;
                int h = tc / 36, rr = tc % 36, p = rr / 3, cd = rr % 3;
                cols[j] = cd*160 + h*20 + 8 + p;   // v_pts columns of wkvp
            }
        }
        for (int k = 0; k < CS_; k++) {
            float wv[4];
            #pragma unroll
            for (int j = 0; j < 4; j++) wv[j] = w0[k*stride + cols[j]];
            #pragma unroll
            for (int r = 0; r < 8; r++) {
                float sv = s_sm[r][k];
                #pragma unroll
                for (int j = 0; j < 4; j++) acc[j][r] += sv * wv[j];
            }
        }
        #pragma unroll
        for (int j = 0; j < 4; j++) {
            int c = c0 + j;
            if (c < 384) {
                float b = bq[c];
                #pragma unroll
                for (int r = 0; r < 8; r++) qraw[r][c] = acc[j][r] + b;
            } else if (c < 1152) {
                int jj = c - 384; float b = bkv[jj];
                int h = jj / 96, rem = jj % 96;
                if (rem < 48) {
                    #pragma unroll
                    for (int r = 0; r < 8; r++) kraw[r][h*48 + rem] = acc[j][r] + b;
                } else {
                    #pragma unroll
                    for (int r = 0; r < 8; r++) g_v[(n0+r)*384 + h*48 + rem - 48] = acc[j][r] + b;
                }
            } else {
                int tc = c - 1152; float b = bkvp[cols[j]];
                #pragma unroll
                for (int r = 0; r < 8; r++) g_vpts[(n0+r)*288 + tc] = acc[j][r] + b;
            }
        }
    }
    __syncthreads();

    // rotation: qh = hw[g]/sqrt3 * R q ; krot = R k   (6144 scalar outputs)
    for (int task = t; task < 6144; task += 256) {
        int r = task / 768, rem = task % 768;
        int isK = rem >= 384;
        int e = isK ? rem - 384 : rem;
        int h = e / 48, g = (e % 48) / 3, i = e % 3;
        const float* src = isK ? &kraw[r][0] : &qraw[r][0];
        float v0 = src[h*48 + g*3 + 0];
        float v1 = src[h*48 + g*3 + 1];
        float v2 = src[h*48 + g*3 + 2];
        float val = rot_sm[r][i*3+0]*v0 + rot_sm[r][i*3+1]*v1 + rot_sm[r][i*3+2]*v2;
        if (isK) g_krot[(n0+r)*384 + e] = val;
        else     g_qh  [(n0+r)*384 + e] = val * hw_sm[g];
    }
}

// ---------------- K2a: qk logits  a[h,n,m] = qh[n,h,:].krot[m,h,:] ----------
__global__ void k_qk()
{
    const int h  = blockIdx.z;
    const int n0 = blockIdx.y * 64;
    const int m0 = blockIdx.x * 64;
    __shared__ float qs[64][49];
    __shared__ float ks[64][49];
    const int t = threadIdx.x;
    for (int e = t; e < 64*48; e += 256) {
        int r = e / 48, c = e % 48;
        qs[r][c] = g_qh  [(n0+r)*384 + h*48 + c];
        ks[r][c] = g_krot[(m0+r)*384 + h*48 + c];
    }
    __syncthreads();
    const int tx = t % 16, ty = t / 16;
    float acc[4][4] = {};
    for (int k = 0; k < 48; k++) {
        float aq[4], bk[4];
        #pragma unroll
        for (int i = 0; i < 4; i++) aq[i] = qs[ty*4+i][k];
        #pragma unroll
        for (int j = 0; j < 4; j++) bk[j] = ks[tx*4+j][k];
        #pragma unroll
        for (int i = 0; i < 4; i++)
            #pragma unroll
            for (int j = 0; j < 4; j++) acc[i][j] += aq[i] * bk[j];
    }
    #pragma unroll
    for (int i = 0; i < 4; i++)
        #pragma unroll
        for (int j = 0; j < 4; j++)
            g_a[h*NSQ + (n0+ty*4+i)*NPT + (m0+tx*4+j)] = acc[i][j];
}

// ---------------- K2b: stream z once, add sqrt(1/3)*(z.wb + bb) ------------
// grid (1024 n, 4 m-tiles) x 64 threads; each thread owns 4 m x 8 h.
__global__ void k_badd(const float* __restrict__ z, const float* __restrict__ wb,
                       const float* __restrict__ bb)
{
    __shared__ float z_sm[256*33];
    __shared__ float wb_sm[32*8];
    const int n  = blockIdx.x;
    const int m0 = blockIdx.y * 256;
    const int t  = threadIdx.x;
    float acc[4][8] = {};
    for (int cz0 = 0; cz0 < 128; cz0 += 32) {
        for (int e = t; e < 256*32; e += 64) {
            int row = e >> 5, c = e & 31;
            z_sm[row*33 + c] = z[(n*NPT + m0 + row)*128 + cz0 + c];
        }
        for (int e = t; e < 256; e += 64) wb_sm[e] = wb[(cz0 + (e>>3))*8 + (e&7)];
        __syncthreads();
        for (int c = 0; c < 32; c++) {
            float wbv[8];
            #pragma unroll
            for (int h = 0; h < 8; h++) wbv[h] = wb_sm[c*8 + h];
            #pragma unroll
            for (int i = 0; i < 4; i++) {
                float zv = z_sm[(t*4 + i)*33 + c];
                #pragma unroll
                for (int h = 0; h < 8; h++) acc[i][h] += zv * wbv[h];
            }
        }
        __syncthreads();
    }
    #pragma unroll
    for (int i = 0; i < 4; i++) {
        int m = m0 + t*4 + i;
        #pragma unroll
        for (int h = 0; h < 8; h++)
            g_a[h*NSQ + n*NPT + m] += 0.57735026918962584f * (acc[i][h] + bb[h]);
    }
}

// ---------------- K3: masked softmax over m -----------------
__global__ void k_softmax(const float* __restrict__ mask)
{
    const int bid = blockIdx.x;
    const int h = bid >> 10, n = bid & 1023;
    float* row = g_a + (size_t)h*NSQ + (size_t)n*NPT;
    const int t = threadIdx.x;
    const float mn = mask[n];
    float x[4]; float mx = -1e30f;
    #pragma unroll
    for (int j = 0; j < 4; j++) {
        int m = t + j*256;
        float xx = row[m] + 100000.0f * (mn * mask[m] - 1.0f);
        x[j] = xx; mx = fmaxf(mx, xx);
    }
    __shared__ float red[8];
    for (int o = 16; o; o >>= 1) mx = fmaxf(mx, __shfl_xor_sync(0xffffffffu, mx, o));
    if ((t & 31) == 0) red[t >> 5] = mx;
    __syncthreads();
    if (t == 0) { float r = red[0]; for (int w = 1; w < 8; w++) r = fmaxf(r, red[w]); red[0] = r; }
    __syncthreads();
    mx = red[0];
    __syncthreads();
    float sum = 0.f;
    #pragma unroll
    for (int j = 0; j < 4; j++) { x[j] = expf(x[j] - mx); sum += x[j]; }
    for (int o = 16; o; o >>= 1) sum += __shfl_xor_sync(0xffffffffu, sum, o);
    if ((t & 31) == 0) red[t >> 5] = sum;
    __syncthreads();
    if (t == 0) { float r = 0.f; for (int w = 0; w < 8; w++) r += red[w]; red[0] = r; }
    __syncthreads();
    const float inv = 1.0f / red[0];
    #pragma unroll
    for (int j = 0; j < 4; j++) row[t + j*256] = x[j] * inv;
}

// ---------------- K4a: zbar[n,h,cz] = sum_m a[h,n,m]*z[n,m,cz] -------------
// grid 1024 x 64 threads; thread owns 4 h x 4 cz.
__global__ void k_zbar(const float* __restrict__ z)
{
    __shared__ __align__(16) float z_sm[16*128];
    __shared__ float a_sm[8*16];
    const int n = blockIdx.x;
    const int t = threadIdx.x;
    const int hg  = t & 1;    // 2 groups of 4 heads
    const int czg = t >> 1;   // 32 groups of 4 cz
    float acc[4][4] = {};
    for (int m0 = 0; m0 < NPT; m0 += 16) {
        for (int e = t; e < 2048; e += 64)
            z_sm[e] = z[(n*NPT + m0 + (e >> 7))*128 + (e & 127)];
        for (int e = t; e < 128; e += 64)
            a_sm[e] = g_a[(e >> 4)*NSQ + n*NPT + m0 + (e & 15)];
        __syncthreads();
        for (int mm = 0; mm < 16; mm++) {
            float4 zv = *reinterpret_cast<const float4*>(&z_sm[mm*128 + czg*4]);
            float av[4];
            #pragma unroll
            for (int hi = 0; hi < 4; hi++) av[hi] = a_sm[(hg*4 + hi)*16 + mm];
            #pragma unroll
            for (int hi = 0; hi < 4; hi++) {
                acc[hi][0] += av[hi]*zv.x; acc[hi][1] += av[hi]*zv.y;
                acc[hi][2] += av[hi]*zv.z; acc[hi][3] += av[hi]*zv.w;
            }
        }
        __syncthreads();
    }
    #pragma unroll
    for (int hi = 0; hi < 4; hi++)
        #pragma unroll
        for (int ci = 0; ci < 4; ci++)
            g_zbar[n*1024 + (hg*4 + hi)*128 + czg*4 + ci] = acc[hi][ci];
}

// ---------------- K4b: o and o_pt = A @ [v | v_pts] per head ----------------
// grid (64 n-tiles, 8 h) x 96 threads; 16 rows x 96 cols (84 valid) per block.
__global__ void k_ov()
{
    __shared__ float a_sm[16*33];
    __shared__ __align__(16) float vv_sm[32*100];
    const int h  = blockIdx.y;
    const int n0 = blockIdx.x * 16;
    const int t  = threadIdx.x;           // 96
    const int rg = t / 24, cg = t % 24;   // 4x4 tile each
    float acc[4][4] = {};
    for (int m0 = 0; m0 < NPT; m0 += 32) {
        for (int e = t; e < 512; e += 96) {
            int r = e >> 5, mm = e & 31;
            a_sm[r*33 + mm] = g_a[h*NSQ + (n0 + r)*NPT + m0 + mm];
        }
        for (int e = t; e < 32*96; e += 96) {
            int mm = e / 96, c = e % 96;
            int m = m0 + mm;
            float val = 0.f;
            if (c < 48)       val = g_v[m*384 + h*48 + c];
            else if (c < 84)  val = g_vpts[m*288 + h*36 + (c - 48)];
            vv_sm[mm*100 + c] = val;
        }
        __syncthreads();
        for (int mm = 0; mm < 32; mm++) {
            float4 bv = *reinterpret_cast<const float4*>(&vv_sm[mm*100 + cg*4]);
            float av[4];
            #pragma unroll
            for (int i = 0; i < 4; i++) av[i] = a_sm[(rg*4 + i)*33 + mm];
            #pragma unroll
            for (int i = 0; i < 4; i++) {
                acc[i][0] += av[i]*bv.x; acc[i][1] += av[i]*bv.y;
                acc[i][2] += av[i]*bv.z; acc[i][3] += av[i]*bv.w;
            }
        }
        __syncthreads();
    }
    #pragma unroll
    for (int i = 0; i < 4; i++) {
        int n = n0 + rg*4 + i;
        #pragma unroll
        for (int j = 0; j < 4; j++) {
            int c = cg*4 + j;
            if (c < 48) {
                g_feats[n*1024 + h*48 + c] = acc[i][j];
            } else if (c < 84) {
                int p = (c - 48) / 3, coord = (c - 48) % 3;
                g_feats[n*1024 + 384 + coord*96 + h*12 + p] = acc[i][j];
            }
        }
    }
}

// ---------------- K5: o_pair = zbar@wdz + bdz, point norms ------------------
__global__ void k_pair_norm(const float* __restrict__ wdz, const float* __restrict__ bdz)
{
    __shared__ float zb[1024];
    const int n = blockIdx.x;
    const int t = threadIdx.x;  // 256
    for (int e = t; e < 1024; e += 256) zb[e] = g_zbar[n*1024 + e];
    __syncthreads();
    {
        const int h = t >> 5, d = t & 31;
        float acc = bdz[d];
        for (int cz = 0; cz < 128; cz++) acc += zb[h*128 + cz] * wdz[cz*32 + d];
        g_feats[n*1024 + 768 + t] = acc;
    }
    if (t < 96) {
        float x  = g_feats[n*1024 + 384 + t];
        float y  = g_feats[n*1024 + 480 + t];
        float zz = g_feats[n*1024 + 576 + t];
        g_feats[n*1024 + 672 + t] = sqrtf(x*x + y*y + zz*zz + 1e-8f);
    }
}

// ---------------- K6: out = feats @ wout + bout -----------------------------
// grid (4 j-tiles, 32 n-tiles) x 256 threads; block 32 n x 96 j; thread 4x3.
__global__ void k_out(const float* __restrict__ wout, const float* __restrict__ bout,
                      float* __restrict__ out)
{
    __shared__ float f_sm[32*65];
    __shared__ float w_sm[64*97];
    const int n0 = blockIdx.y * 32;
    const int j0 = blockIdx.x * 96;
    const int t  = threadIdx.x;
    const int rg = t >> 5, cg = t & 31;
    float acc[4][3] = {};
    for (int e0 = 0; e0 < 1024; e0 += 64) {
        for (int e = t; e < 2048; e += 256) {
            int r = e >> 6, k = e & 63;
            f_sm[r*65 + k] = g_feats[(n0 + r)*1024 + e0 + k];
        }
        for (int e = t; e < 6144; e += 256) {
            int k = e / 96, c = e % 96;
            w_sm[k*97 + c] = wout[(e0 + k)*384 + j0 + c];
        }
        __syncthreads();
        for (int k = 0; k < 64; k++) {
            float av[4], bv[3];
            #pragma unroll
            for (int i = 0; i < 4; i++) av[i] = f_sm[(rg*4 + i)*65 + k];
            #pragma unroll
            for (int j = 0; j < 3; j++) bv[j] = w_sm[k*97 + cg*3 + j];
            #pragma unroll
            for (int i = 0; i < 4; i++)
                #pragma unroll
                for (int j = 0; j < 3; j++) acc[i][j] += av[i] * bv[j];
        }
        __syncthreads();
    }
    #pragma unroll
    for (int i = 0; i < 4; i++) {
        int n = n0 + rg*4 + i;
        #pragma unroll
        for (int j = 0; j < 3; j++) {
            int c = j0 + cg*3 + j;
            out[n*384 + c] = acc[i][j] + bout[c];
        }
    }
}

// ---------------- launch ----------------------------------------------------
extern "C" void kernel_launch(void* const* d_in, const int* in_sizes, int n_in,
                              void* d_out, int out_size)
{
    const float* s    = (const float*)d_in[0];
    const float* z    = (const float*)d_in[1];
    const float* rot  = (const float*)d_in[2];
    const float* mask = (const float*)d_in[3];
    const float* wq   = (const float*)d_in[4];
    const float* bq   = (const float*)d_in[5];
    const float* wkv  = (const float*)d_in[6];
    const float* bkv  = (const float*)d_in[7];
    const float* wkvp = (const float*)d_in[8];
    const float* bkvp = (const float*)d_in[9];
    const float* wb   = (const float*)d_in[10];
    const float* bb   = (const float*)d_in[11];
    const float* wdz  = (const float*)d_in[12];
    const float* bdz  = (const float*)d_in[13];
    const float* wout = (const float*)d_in[14];
    const float* bout = (const float*)d_in[15];
    const float* gw   = (const float*)d_in[16];
    float* out = (float*)d_out;

    k_proj<<<128, 256>>>(s, rot, wq, bq, wkv, bkv, wkvp, bkvp, gw);
    k_qk<<<dim3(16, 16, 8), 256>>>();
    k_badd<<<dim3(1024, 4), 64>>>(z, wb, bb);
    k_softmax<<<8192, 256>>>(mask);
    k_zbar<<<1024, 64>>>(z);
    k_ov<<<dim3(64, 8), 96>>>();
    k_pair_norm<<<1024, 256>>>(wdz, bdz);
    k_out<<<dim3(4, 32), 256>>>(wout, bout, out);
}

// round 6
// speedup vs baseline: 1.0396x; 1.0359x over previous
#include <cuda_runtime.h>
#include <math.h>

#define NPT 1024      // N tokens
#define CS_ 384
#define CZ_ 128
#define H_ 8
#define G_ 16
#define C_ 48
#define PV_ 12
#define CZ4_ 32
#define NSQ (NPT*NPT)

// ---------------- device scratch (no allocations allowed) ----------------
__device__ float g_qh  [NPT*H_*C_];     // rotated+scaled q  (n, h, 48)
__device__ float g_krot[NPT*H_*C_];     // rotated k         (n, h, 48)
__device__ float g_v   [NPT*H_*C_];     // v                 (n, h, 48)
__device__ float g_vpts[NPT*H_*PV_*3];  // v points          (n, h, p, coord)
__device__ float g_a   [H_*NSQ];        // attention logits/probs (h, n, m)
__device__ float g_zbar[NPT*H_*CZ_];    // sum_m a*z          (n, h, 128)
__device__ float g_feats[NPT*1024];     // concat features    (n, 1024)

// ---------------- K1: projections (q,k,v,v_pts) + rotation -----------------
// grid 128 blocks x 256 threads, 8 token rows per block.
__global__ void k_proj(const float* __restrict__ s, const float* __restrict__ rot,
                       const float* __restrict__ wq, const float* __restrict__ bq,
                       const float* __restrict__ wkv, const float* __restrict__ bkv,
                       const float* __restrict__ wkvp, const float* __restrict__ bkvp,
                       const float* __restrict__ gw)
{
    __shared__ float s_sm[8][CS_];
    __shared__ float qraw[8][CS_];
    __shared__ float kraw[8][CS_];
    __shared__ float rot_sm[8][9];
    __shared__ float hw_sm[G_];
    const int t  = threadIdx.x;
    const int n0 = blockIdx.x * 8;

    for (int e = t; e < 8*CS_; e += 256) ((float*)s_sm)[e] = s[n0*CS_ + e];
    for (int e = t; e < 72;     e += 256) ((float*)rot_sm)[e] = rot[n0*9 + e];
    if (t < G_) hw_sm[t] = 0.25f * log1pf(expf(gw[t])) * 0.57735026918962584f;
    __syncthreads();

    // 1440 useful output columns: 384 q | 768 kv | 288 v_pts. groups of 4.
    for (int gt = t; gt < 360; gt += 256) {
        const int c0 = gt * 4;
        float acc[4][8];
        #pragma unroll
        for (int j = 0; j < 4; j++)
            #pragma unroll
            for (int r = 0; r < 8; r++) acc[j][r] = 0.f;

        const float* w0; int stride; int cols[4];
        if (c0 < 384) {
            w0 = wq; stride = 384;
            #pragma unroll
            for (int j = 0; j < 4; j++) cols[j] = c0 + j;
        } else if (c0 < 1152) {
            w0 = wkv; stride = 768;
            #pragma unroll
            for (int j = 0; j < 4; j++) cols[j] = c0 - 384 + j;
        } else {
            w0 = wkvp; stride = 480;
            #pragma unroll
            for (int j = 0; j < 4; j++) {
                int tc = c0 - 1152 + j;
                int h = tc / 36, rr = tc % 36, p = rr / 3, cd = rr % 3;
                cols[j] = cd*160 + h*20 + 8 + p;   // v_pts columns of wkvp
            }
        }
        for (int k = 0; k < CS_; k++) {
            float wv[4];
            #pragma unroll
            for (int j = 0; j < 4; j++) wv[j] = w0[k*stride + cols[j]];
            #pragma unroll
            for (int r = 0; r < 8; r++) {
                float sv = s_sm[r][k];
                #pragma unroll
                for (int j = 0; j < 4; j++) acc[j][r] += sv * wv[j];
            }
        }
        #pragma unroll
        for (int j = 0; j < 4; j++) {
            int c = c0 + j;
            if (c < 384) {
                float b = bq[c];
                #pragma unroll
                for (int r = 0; r < 8; r++) qraw[r][c] = acc[j][r] + b;
            } else if (c < 1152) {
                int jj = c - 384; float b = bkv[jj];
                int h = jj / 96, rem = jj % 96;
                if (rem < 48) {
                    #pragma unroll
                    for (int r = 0; r < 8; r++) kraw[r][h*48 + rem] = acc[j][r] + b;
                } else {
                    #pragma unroll
                    for (int r = 0; r < 8; r++) g_v[(n0+r)*384 + h*48 + rem - 48] = acc[j][r] + b;
                }
            } else {
                int tc = c - 1152; float b = bkvp[cols[j]];
                #pragma unroll
                for (int r = 0; r < 8; r++) g_vpts[(n0+r)*288 + tc] = acc[j][r] + b;
            }
        }
    }
    __syncthreads();

    // rotation: qh = hw[g]/sqrt3 * R q ; krot = R k   (6144 scalar outputs)
    for (int task = t; task < 6144; task += 256) {
        int r = task / 768, rem = task % 768;
        int isK = rem >= 384;
        int e = isK ? rem - 384 : rem;
        int h = e / 48, g = (e % 48) / 3, i = e % 3;
        const float* src = isK ? &kraw[r][0] : &qraw[r][0];
        float v0 = src[h*48 + g*3 + 0];
        float v1 = src[h*48 + g*3 + 1];
        float v2 = src[h*48 + g*3 + 2];
        float val = rot_sm[r][i*3+0]*v0 + rot_sm[r][i*3+1]*v1 + rot_sm[r][i*3+2]*v2;
        if (isK) g_krot[(n0+r)*384 + e] = val;
        else     g_qh  [(n0+r)*384 + e] = val * hw_sm[g];
    }
}

// ---------------- K2a: qk logits  a[h,n,m] = qh[n,h,:].krot[m,h,:] ----------
__global__ void k_qk()
{
    const int h  = blockIdx.z;
    const int n0 = blockIdx.y * 64;
    const int m0 = blockIdx.x * 64;
    __shared__ float qs[64][49];
    __shared__ float ks[64][49];
    const int t = threadIdx.x;
    for (int e = t; e < 64*48; e += 256) {
        int r = e / 48, c = e % 48;
        qs[r][c] = g_qh  [(n0+r)*384 + h*48 + c];
        ks[r][c] = g_krot[(m0+r)*384 + h*48 + c];
    }
    __syncthreads();
    const int tx = t % 16, ty = t / 16;
    float acc[4][4] = {};
    for (int k = 0; k < 48; k++) {
        float aq[4], bk[4];
        #pragma unroll
        for (int i = 0; i < 4; i++) aq[i] = qs[ty*4+i][k];
        #pragma unroll
        for (int j = 0; j < 4; j++) bk[j] = ks[tx*4+j][k];
        #pragma unroll
        for (int i = 0; i < 4; i++)
            #pragma unroll
            for (int j = 0; j < 4; j++) acc[i][j] += aq[i] * bk[j];
    }
    #pragma unroll
    for (int i = 0; i < 4; i++)
        #pragma unroll
        for (int j = 0; j < 4; j++)
            g_a[h*NSQ + (n0+ty*4+i)*NPT + (m0+tx*4+j)] = acc[i][j];
}

// ---------------- K2b: stream z once, add sqrt(1/3)*(z.wb + bb) ------------
// grid (1024 n, 4 m-tiles) x 64 threads; each thread owns 4 m x 8 h.
__global__ void k_badd(const float* __restrict__ z, const float* __restrict__ wb,
                       const float* __restrict__ bb)
{
    __shared__ float z_sm[256*33];
    __shared__ float wb_sm[32*8];
    const int n  = blockIdx.x;
    const int m0 = blockIdx.y * 256;
    const int t  = threadIdx.x;
    float acc[4][8] = {};
    for (int cz0 = 0; cz0 < 128; cz0 += 32) {
        for (int e = t; e < 256*32; e += 64) {
            int row = e >> 5, c = e & 31;
            z_sm[row*33 + c] = z[(n*NPT + m0 + row)*128 + cz0 + c];
        }
        for (int e = t; e < 256; e += 64) wb_sm[e] = wb[(cz0 + (e>>3))*8 + (e&7)];
        __syncthreads();
        for (int c = 0; c < 32; c++) {
            float wbv[8];
            #pragma unroll
            for (int h = 0; h < 8; h++) wbv[h] = wb_sm[c*8 + h];
            #pragma unroll
            for (int i = 0; i < 4; i++) {
                float zv = z_sm[(t*4 + i)*33 + c];
                #pragma unroll
                for (int h = 0; h < 8; h++) acc[i][h] += zv * wbv[h];
            }
        }
        __syncthreads();
    }
    #pragma unroll
    for (int i = 0; i < 4; i++) {
        int m = m0 + t*4 + i;
        #pragma unroll
        for (int h = 0; h < 8; h++)
            g_a[h*NSQ + n*NPT + m] += 0.57735026918962584f * (acc[i][h] + bb[h]);
    }
}

// ---------------- K3: masked softmax over m -----------------
__global__ void k_softmax(const float* __restrict__ mask)
{
    const int bid = blockIdx.x;
    const int h = bid >> 10, n = bid & 1023;
    float* row = g_a + (size_t)h*NSQ + (size_t)n*NPT;
    const int t = threadIdx.x;
    const float mn = mask[n];
    float x[4]; float mx = -1e30f;
    #pragma unroll
    for (int j = 0; j < 4; j++) {
        int m = t + j*256;
        float xx = row[m] + 100000.0f * (mn * mask[m] - 1.0f);
        x[j] = xx; mx = fmaxf(mx, xx);
    }
    __shared__ float red[8];
    for (int o = 16; o; o >>= 1) mx = fmaxf(mx, __shfl_xor_sync(0xffffffffu, mx, o));
    if ((t & 31) == 0) red[t >> 5] = mx;
    __syncthreads();
    if (t == 0) { float r = red[0]; for (int w = 1; w < 8; w++) r = fmaxf(r, red[w]); red[0] = r; }
    __syncthreads();
    mx = red[0];
    __syncthreads();
    float sum = 0.f;
    #pragma unroll
    for (int j = 0; j < 4; j++) { x[j] = expf(x[j] - mx); sum += x[j]; }
    for (int o = 16; o; o >>= 1) sum += __shfl_xor_sync(0xffffffffu, sum, o);
    if ((t & 31) == 0) red[t >> 5] = sum;
    __syncthreads();
    if (t == 0) { float r = 0.f; for (int w = 0; w < 8; w++) r += red[w]; red[0] = r; }
    __syncthreads();
    const float inv = 1.0f / red[0];
    #pragma unroll
    for (int j = 0; j < 4; j++) row[t + j*256] = x[j] * inv;
}

// ---------------- K4a: zbar[n,h,cz] = sum_m a[h,n,m]*z[n,m,cz] -------------
// grid 1024 x 64 threads; thread owns 4 h x 4 cz.
__global__ void k_zbar(const float* __restrict__ z)
{
    __shared__ __align__(16) float z_sm[16*128];
    __shared__ float a_sm[8*16];
    const int n = blockIdx.x;
    const int t = threadIdx.x;
    const int hg  = t & 1;    // 2 groups of 4 heads
    const int czg = t >> 1;   // 32 groups of 4 cz
    float acc[4][4] = {};
    for (int m0 = 0; m0 < NPT; m0 += 16) {
        for (int e = t; e < 2048; e += 64)
            z_sm[e] = z[(n*NPT + m0 + (e >> 7))*128 + (e & 127)];
        for (int e = t; e < 128; e += 64)
            a_sm[e] = g_a[(e >> 4)*NSQ + n*NPT + m0 + (e & 15)];
        __syncthreads();
        for (int mm = 0; mm < 16; mm++) {
            float4 zv = *reinterpret_cast<const float4*>(&z_sm[mm*128 + czg*4]);
            float av[4];
            #pragma unroll
            for (int hi = 0; hi < 4; hi++) av[hi] = a_sm[(hg*4 + hi)*16 + mm];
            #pragma unroll
            for (int hi = 0; hi < 4; hi++) {
                acc[hi][0] += av[hi]*zv.x; acc[hi][1] += av[hi]*zv.y;
                acc[hi][2] += av[hi]*zv.z; acc[hi][3] += av[hi]*zv.w;
            }
        }
        __syncthreads();
    }
    #pragma unroll
    for (int hi = 0; hi < 4; hi++)
        #pragma unroll
        for (int ci = 0; ci < 4; ci++)
            g_zbar[n*1024 + (hg*4 + hi)*128 + czg*4 + ci] = acc[hi][ci];
}

// ---------------- K4b: o and o_pt = A @ [v | v_pts] per head ----------------
// grid (64 n-tiles, 8 h) x 96 threads; 16 rows x 96 cols (84 valid) per block.
__global__ void k_ov()
{
    __shared__ float a_sm[16*33];
    __shared__ __align__(16) float vv_sm[32*100];
    const int h  = blockIdx.y;
    const int n0 = blockIdx.x * 16;
    const int t  = threadIdx.x;           // 96
    const int rg = t / 24, cg = t % 24;   // 4x4 tile each
    float acc[4][4] = {};
    for (int m0 = 0; m0 < NPT; m0 += 32) {
        for (int e = t; e < 512; e += 96) {
            int r = e >> 5, mm = e & 31;
            a_sm[r*33 + mm] = g_a[h*NSQ + (n0 + r)*NPT + m0 + mm];
        }
        for (int e = t; e < 32*96; e += 96) {
            int mm = e / 96, c = e % 96;
            int m = m0 + mm;
            float val = 0.f;
            if (c < 48)       val = g_v[m*384 + h*48 + c];
            else if (c < 84)  val = g_vpts[m*288 + h*36 + (c - 48)];
            vv_sm[mm*100 + c] = val;
        }
        __syncthreads();
        for (int mm = 0; mm < 32; mm++) {
            float4 bv = *reinterpret_cast<const float4*>(&vv_sm[mm*100 + cg*4]);
            float av[4];
            #pragma unroll
            for (int i = 0; i < 4; i++) av[i] = a_sm[(rg*4 + i)*33 + mm];
            #pragma unroll
            for (int i = 0; i < 4; i++) {
                acc[i][0] += av[i]*bv.x; acc[i][1] += av[i]*bv.y;
                acc[i][2] += av[i]*bv.z; acc[i][3] += av[i]*bv.w;
            }
        }
        __syncthreads();
    }
    #pragma unroll
    for (int i = 0; i < 4; i++) {
        int n = n0 + rg*4 + i;
        #pragma unroll
        for (int j = 0; j < 4; j++) {
            int c = cg*4 + j;
            if (c < 48) {
                g_feats[n*1024 + h*48 + c] = acc[i][j];
            } else if (c < 84) {
                int p = (c - 48) / 3, coord = (c - 48) % 3;
                g_feats[n*1024 + 384 + coord*96 + h*12 + p] = acc[i][j];
            }
        }
    }
}

// ---------------- K5: o_pair = zbar@wdz + bdz, point norms ------------------
__global__ void k_pair_norm(const float* __restrict__ wdz, const float* __restrict__ bdz)
{
    __shared__ float zb[1024];
    const int n = blockIdx.x;
    const int t = threadIdx.x;  // 256
    for (int e = t; e < 1024; e += 256) zb[e] = g_zbar[n*1024 + e];
    __syncthreads();
    {
        const int h = t >> 5, d = t & 31;
        float acc = bdz[d];
        for (int cz = 0; cz < 128; cz++) acc += zb[h*128 + cz] * wdz[cz*32 + d];
        g_feats[n*1024 + 768 + t] = acc;
    }
    if (t < 96) {
        float x  = g_feats[n*1024 + 384 + t];
        float y  = g_feats[n*1024 + 480 + t];
        float zz = g_feats[n*1024 + 576 + t];
        g_feats[n*1024 + 672 + t] = sqrtf(x*x + y*y + zz*zz + 1e-8f);
    }
}

// ---------------- K6: out = feats @ wout + bout -----------------------------
// grid (4 j-tiles, 32 n-tiles) x 256 threads; block 32 n x 96 j; thread 4x3.
__global__ void k_out(const float* __restrict__ wout, const float* __restrict__ bout,
                      float* __restrict__ out)
{
    __shared__ float f_sm[32*65];
    __shared__ float w_sm[64*97];
    const int n0 = blockIdx.y * 32;
    const int j0 = blockIdx.x * 96;
    const int t  = threadIdx.x;
    const int rg = t >> 5, cg = t & 31;
    float acc[4][3] = {};
    for (int e0 = 0; e0 < 1024; e0 += 64) {
        for (int e = t; e < 2048; e += 256) {
            int r = e >> 6, k = e & 63;
            f_sm[r*65 + k] = g_feats[(n0 + r)*1024 + e0 + k];
        }
        for (int e = t; e < 6144; e += 256) {
            int k = e / 96, c = e % 96;
            w_sm[k*97 + c] = wout[(e0 + k)*384 + j0 + c];
        }
        __syncthreads();
        for (int k = 0; k < 64; k++) {
            float av[4], bv[3];
            #pragma unroll
            for (int i = 0; i < 4; i++) av[i] = f_sm[(rg*4 + i)*65 + k];
            #pragma unroll
            for (int j = 0; j < 3; j++) bv[j] = w_sm[k*97 + cg*3 + j];
            #pragma unroll
            for (int i = 0; i < 4; i++)
                #pragma unroll
                for (int j = 0; j < 3; j++) acc[i][j] += av[i] * bv[j];
        }
        __syncthreads();
    }
    #pragma unroll
    for (int i = 0; i < 4; i++) {
        int n = n0 + rg*4 + i;
        #pragma unroll
        for (int j = 0; j < 3; j++) {
            int c = j0 + cg*3 + j;
            out[n*384 + c] = acc[i][j] + bout[c];
        }
    }
}

// ---------------- launch ----------------------------------------------------
extern "C" void kernel_launch(void* const* d_in, const int* in_sizes, int n_in,
                              void* d_out, int out_size)
{
    const float* s    = (const float*)d_in[0];
    const float* z    = (const float*)d_in[1];
    const float* rot  = (const float*)d_in[2];
    const float* mask = (const float*)d_in[3];
    const float* wq   = (const float*)d_in[4];
    const float* bq   = (const float*)d_in[5];
    const float* wkv  = (const float*)d_in[6];
    const float* bkv  = (const float*)d_in[7];
    const float* wkvp = (const float*)d_in[8];
    const float* bkvp = (const float*)d_in[9];
    const float* wb   = (const float*)d_in[10];
    const float* bb   = (const float*)d_in[11];
    const float* wdz  = (const float*)d_in[12];
    const float* bdz  = (const float*)d_in[13];
    const float* wout = (const float*)d_in[14];
    const float* bout = (const float*)d_in[15];
    const float* gw   = (const float*)d_in[16];
    float* out = (float*)d_out;

    k_proj<<<128, 256>>>(s, rot, wq, bq, wkv, bkv, wkvp, bkvp, gw);
    k_qk<<<dim3(16, 16, 8), 256>>>();
    k_badd<<<dim3(1024, 4), 64>>>(z, wb, bb);
    k_softmax<<<8192, 256>>>(mask);
    k_zbar<<<1024, 64>>>(z);
    k_ov<<<dim3(64, 8), 96>>>();
    k_pair_norm<<<1024, 256>>>(wdz, bdz);
    k_out<<<dim3(4, 32), 256>>>(wout, bout, out);
}

// round 7
// speedup vs baseline: 1.6662x; 1.6028x over previous
#include <cuda_runtime.h>
#include <math.h>
#include <stdint.h>

#define NPT 1024      // N tokens
#define CS_ 384
#define CZ_ 128
#define H_ 8
#define G_ 16
#define C_ 48
#define PV_ 12
#define CZ4_ 32
#define NSQ (NPT*NPT)

// ---------------- device scratch (no allocations allowed) ----------------
__device__ float g_qh  [NPT*H_*C_];     // rotated+scaled q  (n, h, 48)
__device__ float g_krot[NPT*H_*C_];     // rotated k         (n, h, 48)
__device__ float g_v   [NPT*H_*C_];     // v                 (n, h, 48)
__device__ float g_vpts[NPT*H_*PV_*3];  // v points          (n, h, p, coord)
__device__ float g_a   [H_*NSQ];        // attention logits/probs (h, n, m)
__device__ float g_feats[NPT*1024];     // concat features    (n, 1024)

__device__ __forceinline__ void cp_async16(void* smem_ptr, const void* gptr) {
    uint32_t saddr = (uint32_t)__cvta_generic_to_shared(smem_ptr);
    asm volatile("cp.async.cg.shared.global [%0], [%1], 16;" :: "r"(saddr), "l"(gptr));
}
__device__ __forceinline__ void cp_commit() {
    asm volatile("cp.async.commit_group;");
}
template<int N> __device__ __forceinline__ void cp_wait() {
    asm volatile("cp.async.wait_group %0;" :: "n"(N));
}

// ---------------- K1: projections (q,k,v,v_pts) + rotation -----------------
// grid 128 blocks x 256 threads, 8 token rows per block.
__global__ void k_proj(const float* __restrict__ s, const float* __restrict__ rot,
                       const float* __restrict__ wq, const float* __restrict__ bq,
                       const float* __restrict__ wkv, const float* __restrict__ bkv,
                       const float* __restrict__ wkvp, const float* __restrict__ bkvp,
                       const float* __restrict__ gw)
{
    __shared__ float s_sm[8][CS_];
    __shared__ float qraw[8][CS_];
    __shared__ float kraw[8][CS_];
    __shared__ float rot_sm[8][9];
    __shared__ float hw_sm[G_];
    const int t  = threadIdx.x;
    const int n0 = blockIdx.x * 8;

    for (int e = t; e < 8*CS_; e += 256) ((float*)s_sm)[e] = s[n0*CS_ + e];
    for (int e = t; e < 72;     e += 256) ((float*)rot_sm)[e] = rot[n0*9 + e];
    if (t < G_) hw_sm[t] = 0.25f * log1pf(expf(gw[t])) * 0.57735026918962584f;
    __syncthreads();

    // 1440 useful output columns: 384 q | 768 kv | 288 v_pts. groups of 4.
    for (int gt = t; gt < 360; gt += 256) {
        const int c0 = gt * 4;
        float acc[4][8];
        #pragma unroll
        for (int j = 0; j < 4; j++)
            #pragma unroll
            for (int r = 0; r < 8; r++) acc[j][r] = 0.f;

        const float* w0; int stride; int cols[4];
        if (c0 < 384) {
            w0 = wq; stride = 384;
            #pragma unroll
            for (int j = 0; j < 4; j++) cols[j] = c0 + j;
        } else if (c0 < 1152) {
            w0 = wkv; stride = 768;
            #pragma unroll
            for (int j = 0; j < 4; j++) cols[j] = c0 - 384 + j;
        } else {
            w0 = wkvp; stride = 480;
            #pragma unroll
            for (int j = 0; j < 4; j++) {
                int tc = c0 - 1152 + j;
                int h = tc / 36, rr = tc % 36, p = rr / 3, cd = rr % 3;
                cols[j] = cd*160 + h*20 + 8 + p;   // v_pts columns of wkvp
            }
        }
        for (int k = 0; k < CS_; k++) {
            float wv[4];
            #pragma unroll
            for (int j = 0; j < 4; j++) wv[j] = w0[k*stride + cols[j]];
            #pragma unroll
            for (int r = 0; r < 8; r++) {
                float sv = s_sm[r][k];
                #pragma unroll
                for (int j = 0; j < 4; j++) acc[j][r] += sv * wv[j];
            }
        }
        #pragma unroll
        for (int j = 0; j < 4; j++) {
            int c = c0 + j;
            if (c < 384) {
                float b = bq[c];
                #pragma unroll
                for (int r = 0; r < 8; r++) qraw[r][c] = acc[j][r] + b;
            } else if (c < 1152) {
                int jj = c - 384; float b = bkv[jj];
                int h = jj / 96, rem = jj % 96;
                if (rem < 48) {
                    #pragma unroll
                    for (int r = 0; r < 8; r++) kraw[r][h*48 + rem] = acc[j][r] + b;
                } else {
                    #pragma unroll
                    for (int r = 0; r < 8; r++) g_v[(n0+r)*384 + h*48 + rem - 48] = acc[j][r] + b;
                }
            } else {
                int tc = c - 1152; float b = bkvp[cols[j]];
                #pragma unroll
                for (int r = 0; r < 8; r++) g_vpts[(n0+r)*288 + tc] = acc[j][r] + b;
            }
        }
    }
    __syncthreads();

    // rotation: qh = hw[g]/sqrt3 * R q ; krot = R k   (6144 scalar outputs)
    for (int task = t; task < 6144; task += 256) {
        int r = task / 768, rem = task % 768;
        int isK = rem >= 384;
        int e = isK ? rem - 384 : rem;
        int h = e / 48, g = (e % 48) / 3, i = e % 3;
        const float* src = isK ? &kraw[r][0] : &qraw[r][0];
        float v0 = src[h*48 + g*3 + 0];
        float v1 = src[h*48 + g*3 + 1];
        float v2 = src[h*48 + g*3 + 2];
        float val = rot_sm[r][i*3+0]*v0 + rot_sm[r][i*3+1]*v1 + rot_sm[r][i*3+2]*v2;
        if (isK) g_krot[(n0+r)*384 + e] = val;
        else     g_qh  [(n0+r)*384 + e] = val * hw_sm[g];
    }
}

// ---------------- K2: qk logits  a[h,n,m] = qh[n,h,:].krot[m,h,:] ----------
__global__ void k_qk()
{
    const int h  = blockIdx.z;
    const int n0 = blockIdx.y * 64;
    const int m0 = blockIdx.x * 64;
    __shared__ float qs[64][49];
    __shared__ float ks[64][49];
    const int t = threadIdx.x;
    for (int e = t; e < 64*48; e += 256) {
        int r = e / 48, c = e % 48;
        qs[r][c] = g_qh  [(n0+r)*384 + h*48 + c];
        ks[r][c] = g_krot[(m0+r)*384 + h*48 + c];
    }
    __syncthreads();
    const int tx = t % 16, ty = t / 16;
    float acc[4][4] = {};
    for (int k = 0; k < 48; k++) {
        float aq[4], bk[4];
        #pragma unroll
        for (int i = 0; i < 4; i++) aq[i] = qs[ty*4+i][k];
        #pragma unroll
        for (int j = 0; j < 4; j++) bk[j] = ks[tx*4+j][k];
        #pragma unroll
        for (int i = 0; i < 4; i++)
            #pragma unroll
            for (int j = 0; j < 4; j++) acc[i][j] += aq[i] * bk[j];
    }
    #pragma unroll
    for (int i = 0; i < 4; i++)
        #pragma unroll
        for (int j = 0; j < 4; j++)
            g_a[h*NSQ + (n0+ty*4+i)*NPT + (m0+tx*4+j)] = acc[i][j];
}

// ---------------- K3: fused  bias(z@wb) + softmax + zbar(a@z) + o_pair ------
// One block per token row n; 512 threads; z row (1024x128 = 512KB) streamed
// twice with cp.async double buffering (second pass largely L2-resident).
//
// dynamic smem layout (floats):
//   a_sm : 8 x 1025            (8200)   logits -> probs
//   z_sm : 2 x 64 x 132        (16896)  z tile double buffer
//   wbT  : 8 x 132             (1056)   wb transposed [h][cz]
#define FZ_A    0
#define FZ_Z    8200
#define FZ_WBT  (8200 + 16896)
#define FZ_TOTAL (8200 + 16896 + 1056)

__global__ void __launch_bounds__(512) k_fused(const float* __restrict__ z,
        const float* __restrict__ wb, const float* __restrict__ bb,
        const float* __restrict__ mask,
        const float* __restrict__ wdz, const float* __restrict__ bdz)
{
    extern __shared__ float dsm[];
    float* a_sm = dsm + FZ_A;
    float* z_sm = dsm + FZ_Z;
    float* wbT  = dsm + FZ_WBT;
    __shared__ __align__(16) float comb[1024];
    __shared__ float redmax[8][2];
    __shared__ float redsum[8][2];
    __shared__ float bb_sm[8];

    const int n = blockIdx.x;
    const int t = threadIdx.x;
    const float* zrow_g = z + (size_t)n * NPT * CZ_;

    // issue prefetch of tile 0 (phase A) immediately
    {
        #pragma unroll
        for (int k = 0; k < 4; k++) {
            int idx = t + k*512;             // 2048 float4
            int row = idx >> 5, c4 = idx & 31;
            cp_async16(z_sm + row*132 + c4*4, zrow_g + row*128 + c4*4);
        }
        cp_commit();
    }

    // load logits, wbT, bb while tile0 in flight
    for (int e = t; e < 8192; e += 512) {
        int h = e >> 10, m = e & 1023;
        a_sm[h*1025 + m] = g_a[(size_t)h*NSQ + n*NPT + m];
    }
    for (int e = t; e < 1024; e += 512) {
        int cz = e >> 3, h = e & 7;
        wbT[h*132 + cz] = wb[e];
    }
    if (t < 8) bb_sm[t] = bb[t];

    const int mA = t >> 3;     // 0..63
    const int hA = t & 7;      // 0..7

    // ---------------- phase A: bias = sqrt(1/3)*(z@wb + bb) added to logits
    for (int tile = 0; tile < 16; tile++) {
        const int buf = tile & 1;
        if (tile + 1 < 16) {
            const float* gsrc = zrow_g + (tile+1)*64*128;
            float* sdst = z_sm + (buf^1)*8448;
            #pragma unroll
            for (int k = 0; k < 4; k++) {
                int idx = t + k*512;
                int row = idx >> 5, c4 = idx & 31;
                cp_async16(sdst + row*132 + c4*4, gsrc + row*128 + c4*4);
            }
            cp_commit();
            cp_wait<1>();
        } else {
            cp_wait<0>();
        }
        __syncthreads();

        const float4* zr = reinterpret_cast<const float4*>(z_sm + buf*8448 + mA*132);
        const float4* wr = reinterpret_cast<const float4*>(wbT + hA*132);
        float acc = 0.f;
        #pragma unroll
        for (int c4 = 0; c4 < 32; c4++) {
            float4 zv = zr[c4];
            float4 wv = wr[c4];
            acc += zv.x*wv.x + zv.y*wv.y + zv.z*wv.z + zv.w*wv.w;
        }
        a_sm[hA*1025 + tile*64 + mA] += 0.57735026918962584f * (acc + bb_sm[hA]);
        __syncthreads();
    }

    // prefetch phase-B tile 0 while doing softmax
    {
        #pragma unroll
        for (int k = 0; k < 4; k++) {
            int idx = t + k*512;
            int row = idx >> 5, c4 = idx & 31;
            cp_async16(z_sm + row*132 + c4*4, zrow_g + row*128 + c4*4);
        }
        cp_commit();
    }

    // ---------------- softmax over m (8 heads, 2 warps/head) -----------------
    {
        const int warp = t >> 5, lane = t & 31;
        const int h = warp >> 1, half = warp & 1;
        const int sub = half*32 + lane;      // 0..63
        const float mn = mask[n];
        float local[16];
        float mx = -1e30f;
        #pragma unroll
        for (int j = 0; j < 16; j++) {
            int m = sub + j*64;
            float v = a_sm[h*1025 + m] + 100000.0f * (mn * mask[m] - 1.0f);
            local[j] = v; mx = fmaxf(mx, v);
        }
        #pragma unroll
        for (int o = 16; o; o >>= 1) mx = fmaxf(mx, __shfl_xor_sync(0xffffffffu, mx, o));
        if (lane == 0) redmax[h][half] = mx;
        __syncthreads();
        mx = fmaxf(redmax[h][0], redmax[h][1]);
        float sum = 0.f;
        #pragma unroll
        for (int j = 0; j < 16; j++) { float e = __expf(local[j] - mx); local[j] = e; sum += e; }
        #pragma unroll
        for (int o = 16; o; o >>= 1) sum += __shfl_xor_sync(0xffffffffu, sum, o);
        if (lane == 0) redsum[h][half] = sum;
        __syncthreads();
        const float inv = 1.0f / (redsum[h][0] + redsum[h][1]);
        float* grow = g_a + (size_t)h*NSQ + (size_t)n*NPT;
        #pragma unroll
        for (int j = 0; j < 16; j++) {
            int m = sub + j*64;
            float p = local[j] * inv;
            a_sm[h*1025 + m] = p;
            grow[m] = p;                      // probs for k_ov
        }
    }
    __syncthreads();

    // ---------------- phase B: zbar[h][cz] = sum_m a[h][m] * z[m][cz] --------
    const int czg = t & 31;          // 32 groups of 4 cz
    const int hh  = (t >> 5) & 7;    // head
    const int mh  = t >> 8;          // m-half within tile
    float4 acc4 = make_float4(0.f, 0.f, 0.f, 0.f);

    for (int tile = 0; tile < 16; tile++) {
        const int buf = tile & 1;
        if (tile + 1 < 16) {
            const float* gsrc = zrow_g + (tile+1)*64*128;
            float* sdst = z_sm + (buf^1)*8448;
            #pragma unroll
            for (int k = 0; k < 4; k++) {
                int idx = t + k*512;
                int row = idx >> 5, c4 = idx & 31;
                cp_async16(sdst + row*132 + c4*4, gsrc + row*128 + c4*4);
            }
            cp_commit();
            cp_wait<1>();
        } else {
            cp_wait<0>();
        }
        __syncthreads();

        const float* ar = a_sm + hh*1025 + tile*64 + mh*32;
        const float* zb = z_sm + buf*8448 + (mh*32)*132 + czg*4;
        #pragma unroll
        for (int mm = 0; mm < 32; mm++) {
            float a  = ar[mm];
            float4 zv = *reinterpret_cast<const float4*>(zb + mm*132);
            acc4.x += a*zv.x; acc4.y += a*zv.y; acc4.z += a*zv.z; acc4.w += a*zv.w;
        }
        __syncthreads();
    }

    // combine the two m-halves, stash zbar into a_sm[0..1023]
    if (mh) reinterpret_cast<float4*>(comb)[t - 256] = acc4;
    __syncthreads();
    if (!mh) {
        float4 o = reinterpret_cast<float4*>(comb)[t];
        acc4.x += o.x; acc4.y += o.y; acc4.z += o.z; acc4.w += o.w;
        float* zs = a_sm + hh*128 + czg*4;
        zs[0] = acc4.x; zs[1] = acc4.y; zs[2] = acc4.z; zs[3] = acc4.w;
    }
    __syncthreads();

    // o_pair = zbar @ wdz + bdz  -> feats[768..1024)
    if (t < 256) {
        const int h = t >> 5, d = t & 31;
        float acc = bdz[d];
        const float* zs = a_sm + h*128;
        for (int cz = 0; cz < 128; cz++) acc += zs[cz] * wdz[cz*32 + d];
        g_feats[n*1024 + 768 + t] = acc;
    }
}

// ---------------- K4: o and o_pt = A @ [v | v_pts] per head ----------------
// grid (32 n-tiles, 8 h) x 256 threads; 32 rows x 96 cols (84 valid) per block.
__global__ void k_ov()
{
    __shared__ float a_sm[32][33];
    __shared__ float vv_sm[32][100];
    const int h  = blockIdx.y;
    const int n0 = blockIdx.x * 32;
    const int t  = threadIdx.x;           // 256
    const int rg = t >> 5;                // 8 groups of 4 rows
    const int cg = t & 31;                // 32 groups of 3 cols
    float acc[4][3] = {};
    for (int m0 = 0; m0 < NPT; m0 += 32) {
        for (int e = t; e < 1024; e += 256) {
            int r = e >> 5, mm = e & 31;
            a_sm[r][mm] = g_a[(size_t)h*NSQ + (n0 + r)*NPT + m0 + mm];
        }
        for (int e = t; e < 32*96; e += 256) {
            int mm = e / 96, c = e % 96;
            int m = m0 + mm;
            float val = 0.f;
            if (c < 48)       val = g_v[m*384 + h*48 + c];
            else if (c < 84)  val = g_vpts[m*288 + h*36 + (c - 48)];
            vv_sm[mm][c] = val;
        }
        __syncthreads();
        #pragma unroll 4
        for (int mm = 0; mm < 32; mm++) {
            float av[4], bv[3];
            #pragma unroll
            for (int i = 0; i < 4; i++) av[i] = a_sm[rg*4 + i][mm];
            #pragma unroll
            for (int j = 0; j < 3; j++) bv[j] = vv_sm[mm][cg*3 + j];
            #pragma unroll
            for (int i = 0; i < 4; i++)
                #pragma unroll
                for (int j = 0; j < 3; j++) acc[i][j] += av[i] * bv[j];
        }
        __syncthreads();
    }
    #pragma unroll
    for (int i = 0; i < 4; i++) {
        int nn = n0 + rg*4 + i;
        #pragma unroll
        for (int j = 0; j < 3; j++) {
            int c = cg*3 + j;
            if (c < 48) {
                g_feats[nn*1024 + h*48 + c] = acc[i][j];
            } else if (c < 84) {
                int p = (c - 48) / 3, coord = (c - 48) % 3;
                g_feats[nn*1024 + 384 + coord*96 + h*12 + p] = acc[i][j];
            }
        }
    }
}

// ---------------- K5: point norms -------------------------------------------
__global__ void k_norm()
{
    const int n = blockIdx.x;
    const int t = threadIdx.x;
    if (t < 96) {
        float x  = g_feats[n*1024 + 384 + t];
        float y  = g_feats[n*1024 + 480 + t];
        float zz = g_feats[n*1024 + 576 + t];
        g_feats[n*1024 + 672 + t] = sqrtf(x*x + y*y + zz*zz + 1e-8f);
    }
}

// ---------------- K6: out = feats @ wout + bout -----------------------------
// grid (4 j-tiles, 32 n-tiles) x 256 threads; block 32 n x 96 j; thread 4x3.
__global__ void k_out(const float* __restrict__ wout, const float* __restrict__ bout,
                      float* __restrict__ out)
{
    __shared__ float f_sm[32*65];
    __shared__ float w_sm[64*97];
    const int n0 = blockIdx.y * 32;
    const int j0 = blockIdx.x * 96;
    const int t  = threadIdx.x;
    const int rg = t >> 5, cg = t & 31;
    float acc[4][3] = {};
    for (int e0 = 0; e0 < 1024; e0 += 64) {
        for (int e = t; e < 2048; e += 256) {
            int r = e >> 6, k = e & 63;
            f_sm[r*65 + k] = g_feats[(n0 + r)*1024 + e0 + k];
        }
        for (int e = t; e < 6144; e += 256) {
            int k = e / 96, c = e % 96;
            w_sm[k*97 + c] = wout[(e0 + k)*384 + j0 + c];
        }
        __syncthreads();
        for (int k = 0; k < 64; k++) {
            float av[4], bv[3];
            #pragma unroll
            for (int i = 0; i < 4; i++) av[i] = f_sm[(rg*4 + i)*65 + k];
            #pragma unroll
            for (int j = 0; j < 3; j++) bv[j] = w_sm[k*97 + cg*3 + j];
            #pragma unroll
            for (int i = 0; i < 4; i++)
                #pragma unroll
                for (int j = 0; j < 3; j++) acc[i][j] += av[i] * bv[j];
        }
        __syncthreads();
    }
    #pragma unroll
    for (int i = 0; i < 4; i++) {
        int n = n0 + rg*4 + i;
        #pragma unroll
        for (int j = 0; j < 3; j++) {
            int c = j0 + cg*3 + j;
            out[n*384 + c] = acc[i][j] + bout[c];
        }
    }
}

// ---------------- launch ----------------------------------------------------
extern "C" void kernel_launch(void* const* d_in, const int* in_sizes, int n_in,
                              void* d_out, int out_size)
{
    const float* s    = (const float*)d_in[0];
    const float* z    = (const float*)d_in[1];
    const float* rot  = (const float*)d_in[2];
    const float* mask = (const float*)d_in[3];
    const float* wq   = (const float*)d_in[4];
    const float* bq   = (const float*)d_in[5];
    const float* wkv  = (const float*)d_in[6];
    const float* bkv  = (const float*)d_in[7];
    const float* wkvp = (const float*)d_in[8];
    const float* bkvp = (const float*)d_in[9];
    const float* wb   = (const float*)d_in[10];
    const float* bb   = (const float*)d_in[11];
    const float* wdz  = (const float*)d_in[12];
    const float* bdz  = (const float*)d_in[13];
    const float* wout = (const float*)d_in[14];
    const float* bout = (const float*)d_in[15];
    const float* gw   = (const float*)d_in[16];
    float* out = (float*)d_out;

    const int fz_bytes = FZ_TOTAL * 4;   // ~104.6 KB dynamic smem
    cudaFuncSetAttribute(k_fused, cudaFuncAttributeMaxDynamicSharedMemorySize, fz_bytes);

    k_proj<<<128, 256>>>(s, rot, wq, bq, wkv, bkv, wkvp, bkvp, gw);
    k_qk<<<dim3(16, 16, 8), 256>>>();
    k_fused<<<1024, 512, fz_bytes>>>(z, wb, bb, mask, wdz, bdz);
    k_ov<<<dim3(32, 8), 256>>>();
    k_norm<<<1024, 96>>>();
    k_out<<<dim3(4, 32), 256>>>(wout, bout, out);
}

// round 9
// speedup vs baseline: 2.2178x; 1.3311x over previous
#include <cuda_runtime.h>
#include <math.h>
#include <stdint.h>

#define NPT 1024      // N tokens
#define CS_ 384
#define CZ_ 128
#define H_ 8
#define G_ 16
#define C_ 48
#define PV_ 12
#define CZ4_ 32
#define NSQ (NPT*NPT)
#define SQ13 0.57735026918962584f

// ---------------- device scratch (no allocations allowed) ----------------
__device__ float g_qh  [NPT*H_*C_];     // rotated+scaled q  (n, h, 48)
__device__ float g_krot[NPT*H_*C_];     // rotated k         (n, h, 48)
__device__ float g_vv  [NPT*H_*96];     // packed [v(48) | vpts(36) | pad(12)]
__device__ float g_a   [H_*NSQ];        // attention logits -> probs (h, n, m)
__device__ float g_feats[NPT*1024];     // concat features    (n, 1024)

__device__ __forceinline__ void cp_async16(void* smem_ptr, const void* gptr) {
    uint32_t saddr = (uint32_t)__cvta_generic_to_shared(smem_ptr);
    asm volatile("cp.async.cg.shared.global [%0], [%1], 16;" :: "r"(saddr), "l"(gptr));
}
__device__ __forceinline__ void cp_commit() {
    asm volatile("cp.async.commit_group;");
}
template<int N> __device__ __forceinline__ void cp_wait() {
    asm volatile("cp.async.wait_group %0;" :: "n"(N));
}

// ---------------- K1: projections (q,k,v,v_pts) + rotation -----------------
__global__ void k_proj(const float* __restrict__ s, const float* __restrict__ rot,
                       const float* __restrict__ wq, const float* __restrict__ bq,
                       const float* __restrict__ wkv, const float* __restrict__ bkv,
                       const float* __restrict__ wkvp, const float* __restrict__ bkvp,
                       const float* __restrict__ gw)
{
    __shared__ float s_sm[8][CS_];
    __shared__ float qraw[8][CS_];
    __shared__ float kraw[8][CS_];
    __shared__ float rot_sm[8][9];
    __shared__ float hw_sm[G_];
    const int t  = threadIdx.x;
    const int n0 = blockIdx.x * 8;

    for (int e = t; e < 8*CS_; e += 256) ((float*)s_sm)[e] = s[n0*CS_ + e];
    for (int e = t; e < 72;     e += 256) ((float*)rot_sm)[e] = rot[n0*9 + e];
    if (t < G_) hw_sm[t] = 0.25f * log1pf(expf(gw[t])) * SQ13;
    __syncthreads();

    // zero pad cols 84..95 of g_vv for this block's 8 rows
    for (int e = t; e < 768; e += 256) {
        int r = e / 96, h = (e % 96) / 12, j = e % 12;
        g_vv[(n0+r)*768 + h*96 + 84 + j] = 0.f;
    }

    for (int gt = t; gt < 360; gt += 256) {
        const int c0 = gt * 4;
        float acc[4][8];
        #pragma unroll
        for (int j = 0; j < 4; j++)
            #pragma unroll
            for (int r = 0; r < 8; r++) acc[j][r] = 0.f;

        const float* w0; int stride; int cols[4];
        if (c0 < 384) {
            w0 = wq; stride = 384;
            #pragma unroll
            for (int j = 0; j < 4; j++) cols[j] = c0 + j;
        } else if (c0 < 1152) {
            w0 = wkv; stride = 768;
            #pragma unroll
            for (int j = 0; j < 4; j++) cols[j] = c0 - 384 + j;
        } else {
            w0 = wkvp; stride = 480;
            #pragma unroll
            for (int j = 0; j < 4; j++) {
                int tc = c0 - 1152 + j;
                int h = tc / 36, rr = tc % 36, p = rr / 3, cd = rr % 3;
                cols[j] = cd*160 + h*20 + 8 + p;   // v_pts columns of wkvp
            }
        }
        for (int k = 0; k < CS_; k++) {
            float wv[4];
            #pragma unroll
            for (int j = 0; j < 4; j++) wv[j] = w0[k*stride + cols[j]];
            #pragma unroll
            for (int r = 0; r < 8; r++) {
                float sv = s_sm[r][k];
                #pragma unroll
                for (int j = 0; j < 4; j++) acc[j][r] += sv * wv[j];
            }
        }
        #pragma unroll
        for (int j = 0; j < 4; j++) {
            int c = c0 + j;
            if (c < 384) {
                float b = bq[c];
                #pragma unroll
                for (int r = 0; r < 8; r++) qraw[r][c] = acc[j][r] + b;
            } else if (c < 1152) {
                int jj = c - 384; float b = bkv[jj];
                int h = jj / 96, rem = jj % 96;
                if (rem < 48) {
                    #pragma unroll
                    for (int r = 0; r < 8; r++) kraw[r][h*48 + rem] = acc[j][r] + b;
                } else {
                    #pragma unroll
                    for (int r = 0; r < 8; r++)
                        g_vv[(n0+r)*768 + h*96 + (rem - 48)] = acc[j][r] + b;
                }
            } else {
                int tc = c - 1152; float b = bkvp[cols[j]];
                int h = tc / 36, rr = tc % 36;
                #pragma unroll
                for (int r = 0; r < 8; r++)
                    g_vv[(n0+r)*768 + h*96 + 48 + rr] = acc[j][r] + b;
            }
        }
    }
    __syncthreads();

    for (int task = t; task < 6144; task += 256) {
        int r = task / 768, rem = task % 768;
        int isK = rem >= 384;
        int e = isK ? rem - 384 : rem;
        int h = e / 48, g = (e % 48) / 3, i = e % 3;
        const float* src = isK ? &kraw[r][0] : &qraw[r][0];
        float v0 = src[h*48 + g*3 + 0];
        float v1 = src[h*48 + g*3 + 1];
        float v2 = src[h*48 + g*3 + 2];
        float val = rot_sm[r][i*3+0]*v0 + rot_sm[r][i*3+1]*v1 + rot_sm[r][i*3+2]*v2;
        if (isK) g_krot[(n0+r)*384 + e] = val;
        else     g_qh  [(n0+r)*384 + e] = val * hw_sm[g];
    }
}

// ---------------- K2: qk logits  a[h,n,m] = qh[n,h,:].krot[m,h,:] ----------
__global__ void k_qk()
{
    const int h  = blockIdx.z;
    const int n0 = blockIdx.y * 64;
    const int m0 = blockIdx.x * 64;
    __shared__ float qs[64][49];
    __shared__ float ks[64][49];
    const int t = threadIdx.x;
    for (int e = t; e < 64*48; e += 256) {
        int r = e / 48, c = e % 48;
        qs[r][c] = g_qh  [(n0+r)*384 + h*48 + c];
        ks[r][c] = g_krot[(m0+r)*384 + h*48 + c];
    }
    __syncthreads();
    const int tx = t % 16, ty = t / 16;
    float acc[4][4] = {};
    for (int k = 0; k < 48; k++) {
        float aq[4], bk[4];
        #pragma unroll
        for (int i = 0; i < 4; i++) aq[i] = qs[ty*4+i][k];
        #pragma unroll
        for (int j = 0; j < 4; j++) bk[j] = ks[tx*4+j][k];
        #pragma unroll
        for (int i = 0; i < 4; i++)
            #pragma unroll
            for (int j = 0; j < 4; j++) acc[i][j] += aq[i] * bk[j];
    }
    #pragma unroll
    for (int i = 0; i < 4; i++)
        #pragma unroll
        for (int j = 0; j < 4; j++)
            g_a[h*NSQ + (n0+ty*4+i)*NPT + (m0+tx*4+j)] = acc[i][j];
}

// ---------------- K3: single-pass fused bias + online softmax + zbar + o_pair
// dynamic smem (floats):
//   a_sm    : 8 x 1025   (8200)   logits -> e values
//   z_sm    : 2 x 64x132 (16896)  z tile double buffer (reused as comb/zbar at end)
//   wbT     : 8 x 132    (1056)
//   partial : 64 x 8 x 2 (1024)   bias cz-split partials
#define FZ_A    0
#define FZ_Z    8200
#define FZ_WBT  (8200 + 16896)
#define FZ_PART (FZ_WBT + 1056)
#define FZ_TOTAL (FZ_PART + 1024)

__global__ void __launch_bounds__(512) k_fused(const float* __restrict__ z,
        const float* __restrict__ wb, const float* __restrict__ bb,
        const float* __restrict__ mask,
        const float* __restrict__ wdz, const float* __restrict__ bdz)
{
    extern __shared__ float dsm[];
    float* a_sm    = dsm + FZ_A;
    float* z_sm    = dsm + FZ_Z;
    float* wbT     = dsm + FZ_WBT;
    float* partial = dsm + FZ_PART;
    __shared__ float redmax[8][2];
    __shared__ float redsum[8][2];
    __shared__ float mx_s[8], sum_s[8], scale_s[8], invs[8];
    __shared__ float tilemx[16*8];
    __shared__ float bb_sm[8];

    const int n = blockIdx.x;
    const int t = threadIdx.x;
    const float* zrow_g = z + (size_t)n * NPT * CZ_;

    // prefetch tile 0
    {
        #pragma unroll
        for (int k = 0; k < 4; k++) {
            int idx = t + k*512;
            int row = idx >> 5, c4 = idx & 31;
            cp_async16(z_sm + row*132 + c4*4, zrow_g + row*128 + c4*4);
        }
        cp_commit();
    }

    // logits (+ mask bias), wbT, bb, init running stats
    const float mn = mask[n];
    for (int e = t; e < 8192; e += 512) {
        int h = e >> 10, m = e & 1023;
        a_sm[h*1025 + m] = g_a[(size_t)h*NSQ + n*NPT + m]
                           + 100000.0f * (mn * mask[m] - 1.0f);
    }
    for (int e = t; e < 1024; e += 512) {
        int cz = e >> 3, h = e & 7;
        wbT[h*132 + cz] = wb[e];
    }
    if (t < 8) { bb_sm[t] = bb[t]; mx_s[t] = -1e30f; sum_s[t] = 0.f; }

    // thread decompositions
    const int hpB = t & 3, mB = (t >> 2) & 63, czh = t >> 8;   // bias
    const int hF = t >> 6, halfF = (t >> 5) & 1, laneF = t & 31;
    const int mF = halfF*32 + laneF;                            // finish/softmax
    const int czg = t & 31, hp = (t >> 5) & 3, mq = t >> 7;     // zbar
    float4 acc0 = {0,0,0,0}, acc1 = {0,0,0,0};

    for (int tile = 0; tile < 16; tile++) {
        const int buf = tile & 1;
        // ensure previous tile's compute (reads of buf^1) is fully done
        // before any thread overwrites buf^1 with the next prefetch.
        __syncthreads();
        if (tile + 1 < 16) {
            const float* gsrc = zrow_g + (tile+1)*64*128;
            float* sdst = z_sm + (buf^1)*8448;
            #pragma unroll
            for (int k = 0; k < 4; k++) {
                int idx = t + k*512;
                int row = idx >> 5, c4 = idx & 31;
                cp_async16(sdst + row*132 + c4*4, gsrc + row*128 + c4*4);
            }
            cp_commit();
            cp_wait<1>();     // 2 groups outstanding -> waits for CURRENT tile
        } else {
            cp_wait<0>();
        }
        __syncthreads();

        // --- bias partials: thread = (hpB, mB, czh), 2 heads x 64 cz each
        {
            const float4* zr = (const float4*)(z_sm + buf*8448 + mB*132 + czh*64);
            const float4* w0 = (const float4*)(wbT + (2*hpB  )*132 + czh*64);
            const float4* w1 = (const float4*)(wbT + (2*hpB+1)*132 + czh*64);
            float a0 = 0.f, a1 = 0.f;
            #pragma unroll
            for (int c4 = 0; c4 < 16; c4++) {
                float4 zv = zr[c4];
                float4 u0 = w0[c4], u1 = w1[c4];
                a0 += zv.x*u0.x + zv.y*u0.y + zv.z*u0.z + zv.w*u0.w;
                a1 += zv.x*u1.x + zv.y*u1.y + zv.z*u1.z + zv.w*u1.w;
            }
            partial[mB*16 + (2*hpB  )*2 + czh] = a0;
            partial[mB*16 + (2*hpB+1)*2 + czh] = a1;
        }
        __syncthreads();

        // --- finish logit l, tile max
        float l;
        {
            float bias = partial[mF*16 + hF*2] + partial[mF*16 + hF*2 + 1];
            l = a_sm[hF*1025 + tile*64 + mF] + SQ13 * (bias + bb_sm[hF]);
            float wm = l;
            #pragma unroll
            for (int o = 16; o; o >>= 1) wm = fmaxf(wm, __shfl_xor_sync(0xffffffffu, wm, o));
            if (laneF == 0) redmax[hF][halfF] = wm;
        }
        __syncthreads();
        if (t < 8) {
            float tm = fmaxf(redmax[t][0], redmax[t][1]);
            float nm = fmaxf(mx_s[t], tm);
            scale_s[t] = __expf(mx_s[t] - nm);
            mx_s[t] = nm;
            tilemx[tile*8 + t] = nm;
        }
        __syncthreads();
        // --- e values + tile sum
        {
            float e = __expf(l - mx_s[hF]);
            a_sm[hF*1025 + tile*64 + mF] = e;
            float ws = e;
            #pragma unroll
            for (int o = 16; o; o >>= 1) ws += __shfl_xor_sync(0xffffffffu, ws, o);
            if (laneF == 0) redsum[hF][halfF] = ws;
        }
        __syncthreads();

        // --- zbar accumulate: thread = (czg, hp, mq), 2 heads each
        {
            const float s0 = scale_s[2*hp], s1 = scale_s[2*hp+1];
            acc0.x *= s0; acc0.y *= s0; acc0.z *= s0; acc0.w *= s0;
            acc1.x *= s1; acc1.y *= s1; acc1.z *= s1; acc1.w *= s1;
            const float* ar0 = a_sm + (2*hp)*1025 + tile*64 + mq*16;
            const float* ar1 = ar0 + 1025;
            const float* zp  = z_sm + buf*8448 + (mq*16)*132 + czg*4;
            #pragma unroll
            for (int mm = 0; mm < 16; mm++) {
                float4 zv = *(const float4*)(zp + mm*132);
                float e0 = ar0[mm], e1 = ar1[mm];
                acc0.x += e0*zv.x; acc0.y += e0*zv.y; acc0.z += e0*zv.z; acc0.w += e0*zv.w;
                acc1.x += e1*zv.x; acc1.y += e1*zv.y; acc1.z += e1*zv.z; acc1.w += e1*zv.w;
            }
        }
        if (t < 8) sum_s[t] = sum_s[t]*scale_s[t] + redsum[t][0] + redsum[t][1];
    }
    __syncthreads();

    // --- reduce zbar quarters (reuse z_sm)
    float* comb = z_sm;
    {
        int cidx = ((mq*4 + hp)*32 + czg)*8;
        *(float4*)(comb + cidx)     = acc0;
        *(float4*)(comb + cidx + 4) = acc1;
    }
    __syncthreads();
    float* zbar_sm = z_sm + 8192;
    if (t < 8) invs[t] = 1.0f / sum_s[t];         // per-head inverse sum (FIXED)
    if (t < 256) {
        int h = t >> 5, cz = t & 31, hp2 = h >> 1, wh = h & 1;
        float4 zb = {0,0,0,0};
        #pragma unroll
        for (int q = 0; q < 4; q++) {
            float4 v = *(const float4*)(comb + ((q*4 + hp2)*32 + cz)*8 + wh*4);
            zb.x += v.x; zb.y += v.y; zb.z += v.z; zb.w += v.w;
        }
        float inv = 1.0f / sum_s[h];
        zb.x *= inv; zb.y *= inv; zb.z *= inv; zb.w *= inv;
        *(float4*)(zbar_sm + h*128 + cz*4) = zb;
    }
    __syncthreads();

    // --- write final probs to g_a:  p = e * exp(tilemx - mx_final) * inv_sum
    for (int e = t; e < 8192; e += 512) {
        int h = e >> 10, m = e & 1023;
        float ev = a_sm[h*1025 + m];
        float p = ev * __expf(tilemx[(m >> 6)*8 + h] - mx_s[h]) * invs[h];
        g_a[(size_t)h*NSQ + n*NPT + m] = p;
    }
    // --- o_pair = zbar @ wdz + bdz
    if (t < 256) {
        const int h = t >> 5, d = t & 31;
        float acc = bdz[d];
        const float* zs = zbar_sm + h*128;
        #pragma unroll 8
        for (int cz = 0; cz < 128; cz++) acc += zs[cz] * wdz[cz*32 + d];
        g_feats[n*1024 + 768 + t] = acc;
    }
}

// ---------------- K4: o and o_pt = A @ [v | v_pts] per head ----------------
// grid (64 n-tiles, 8 h) x 192 threads; tile 16n x 96c; thread 4x4, m-split 2.
__global__ void __launch_bounds__(192) k_ov()
{
    __shared__ __align__(16) float a_sm[2][16*36];
    __shared__ __align__(16) float vv_sm[2][32*104];
    const int h  = blockIdx.y;
    const int n0 = blockIdx.x * 16;
    const int t  = threadIdx.x;
    const int ms = t & 1, rg = (t >> 1) & 3, cg = t >> 3;   // cg 0..23
    const float* ga = g_a + (size_t)h * NSQ;
    const float* gv = g_vv + h * 96;

    // fill tile 0
    {
        if (t < 128) {
            int r = t >> 3, c4 = t & 7;
            cp_async16(&a_sm[0][r*36 + c4*4], ga + (n0 + r)*1024 + c4*4);
        }
        for (int e = t; e < 768; e += 192) {
            int mm = e / 24, c4 = e % 24;
            cp_async16(&vv_sm[0][mm*104 + c4*4], gv + (size_t)mm*768 + c4*4);
        }
        cp_commit();
    }

    float acc[4][4] = {};
    for (int tile = 0; tile < 32; tile++) {
        const int buf = tile & 1;
        if (tile + 1 < 32) {
            const int m0 = (tile + 1) * 32;
            if (t < 128) {
                int r = t >> 3, c4 = t & 7;
                cp_async16(&a_sm[buf^1][r*36 + c4*4], ga + (n0 + r)*1024 + m0 + c4*4);
            }
            for (int e = t; e < 768; e += 192) {
                int mm = e / 24, c4 = e % 24;
                cp_async16(&vv_sm[buf^1][mm*104 + c4*4], gv + (size_t)(m0 + mm)*768 + c4*4);
            }
            cp_commit();
            cp_wait<1>();
        } else {
            cp_wait<0>();
        }
        __syncthreads();

        #pragma unroll
        for (int mm = 0; mm < 16; mm++) {
            const int ml = mm*2 + ms;
            float4 bv = *(const float4*)(&vv_sm[buf][ml*104 + cg*4]);
            float av[4];
            #pragma unroll
            for (int i = 0; i < 4; i++) av[i] = a_sm[buf][(rg*4 + i)*36 + ml];
            #pragma unroll
            for (int i = 0; i < 4; i++) {
                acc[i][0] += av[i]*bv.x; acc[i][1] += av[i]*bv.y;
                acc[i][2] += av[i]*bv.z; acc[i][3] += av[i]*bv.w;
            }
        }
        __syncthreads();
    }

    // combine ms halves via smem (vv_sm free now)
    float* comb = (float*)vv_sm;
    if (ms == 1) {
        float* cb = comb + (rg*24 + cg)*16;
        #pragma unroll
        for (int i = 0; i < 4; i++)
            #pragma unroll
            for (int j = 0; j < 4; j++) cb[i*4 + j] = acc[i][j];
    }
    __syncthreads();
    if (ms == 0) {
        const float* cb = comb + (rg*24 + cg)*16;
        #pragma unroll
        for (int i = 0; i < 4; i++) {
            int nn = n0 + rg*4 + i;
            #pragma unroll
            for (int j = 0; j < 4; j++) {
                float v = acc[i][j] + cb[i*4 + j];
                int c = cg*4 + j;
                if (c < 48) {
                    g_feats[nn*1024 + h*48 + c] = v;
                } else if (c < 84) {
                    int p = (c - 48) / 3, coord = (c - 48) % 3;
                    g_feats[nn*1024 + 384 + coord*96 + h*12 + p] = v;
                }
            }
        }
    }
}

// ---------------- K5: point norms -------------------------------------------
__global__ void k_norm()
{
    const int n = blockIdx.x;
    const int t = threadIdx.x;
    if (t < 96) {
        float x  = g_feats[n*1024 + 384 + t];
        float y  = g_feats[n*1024 + 480 + t];
        float zz = g_feats[n*1024 + 576 + t];
        g_feats[n*1024 + 672 + t] = sqrtf(x*x + y*y + zz*zz + 1e-8f);
    }
}

// ---------------- K6: out = feats @ wout + bout -----------------------------
__global__ void k_out(const float* __restrict__ wout, const float* __restrict__ bout,
                      float* __restrict__ out)
{
    __shared__ float f_sm[32*65];
    __shared__ float w_sm[64*97];
    const int n0 = blockIdx.y * 32;
    const int j0 = blockIdx.x * 96;
    const int t  = threadIdx.x;
    const int rg = t >> 5, cg = t & 31;
    float acc[4][3] = {};
    for (int e0 = 0; e0 < 1024; e0 += 64) {
        for (int e = t; e < 2048; e += 256) {
            int r = e >> 6, k = e & 63;
            f_sm[r*65 + k] = g_feats[(n0 + r)*1024 + e0 + k];
        }
        for (int e = t; e < 6144; e += 256) {
            int k = e / 96, c = e % 96;
            w_sm[k*97 + c] = wout[(e0 + k)*384 + j0 + c];
        }
        __syncthreads();
        for (int k = 0; k < 64; k++) {
            float av[4], bv[3];
            #pragma unroll
            for (int i = 0; i < 4; i++) av[i] = f_sm[(rg*4 + i)*65 + k];
            #pragma unroll
            for (int j = 0; j < 3; j++) bv[j] = w_sm[k*97 + cg*3 + j];
            #pragma unroll
            for (int i = 0; i < 4; i++)
                #pragma unroll
                for (int j = 0; j < 3; j++) acc[i][j] += av[i] * bv[j];
        }
        __syncthreads();
    }
    #pragma unroll
    for (int i = 0; i < 4; i++) {
        int n = n0 + rg*4 + i;
        #pragma unroll
        for (int j = 0; j < 3; j++) {
            int c = j0 + cg*3 + j;
            out[n*384 + c] = acc[i][j] + bout[c];
        }
    }
}

// ---------------- launch ----------------------------------------------------
extern "C" void kernel_launch(void* const* d_in, const int* in_sizes, int n_in,
                              void* d_out, int out_size)
{
    const float* s    = (const float*)d_in[0];
    const float* z    = (const float*)d_in[1];
    const float* rot  = (const float*)d_in[2];
    const float* mask = (const float*)d_in[3];
    const float* wq   = (const float*)d_in[4];
    const float* bq   = (const float*)d_in[5];
    const float* wkv  = (const float*)d_in[6];
    const float* bkv  = (const float*)d_in[7];
    const float* wkvp = (const float*)d_in[8];
    const float* bkvp = (const float*)d_in[9];
    const float* wb   = (const float*)d_in[10];
    const float* bb   = (const float*)d_in[11];
    const float* wdz  = (const float*)d_in[12];
    const float* bdz  = (const float*)d_in[13];
    const float* wout = (const float*)d_in[14];
    const float* bout = (const float*)d_in[15];
    const float* gw   = (const float*)d_in[16];
    float* out = (float*)d_out;

    const int fz_bytes = FZ_TOTAL * 4;   // ~108.7 KB dynamic smem
    cudaFuncSetAttribute(k_fused, cudaFuncAttributeMaxDynamicSharedMemorySize, fz_bytes);

    k_proj<<<128, 256>>>(s, rot, wq, bq, wkv, bkv, wkvp, bkvp, gw);
    k_qk<<<dim3(16, 16, 8), 256>>>();
    k_fused<<<1024, 512, fz_bytes>>>(z, wb, bb, mask, wdz, bdz);
    k_ov<<<dim3(64, 8), 192>>>();
    k_norm<<<1024, 96>>>();
    k_out<<<dim3(4, 32), 256>>>(wout, bout, out);
}